// round 12
// baseline (speedup 1.0000x reference)
#include <cuda_runtime.h>
#include <cuda_bf16.h>
#include <cstdint>
#include <cstddef>

#define DIMC 768
#define HC 12
#define HDC 64
#define BC 4
#define LQC 2048
#define LKC 2048
#define NR (BC * LQC)   // 8192 rows
#define NELT (BC * HC * LQC * HDC)

// ---------------- scratch (no allocations allowed) ----------------
// Q/K/V live only as split bf16 hi/lo (produced by projection epilogues).
__device__ unsigned short g_Qh[NELT], g_Ql[NELT];
__device__ unsigned short g_Kh[NELT], g_Kl[NELT];
__device__ unsigned short g_Vh[NELT], g_Vl[NELT];
__device__ float g_AO[BC * LQC * DIMC];      // (b,l,dim) fp32

// =====================================================================
// mma.sync helpers (compute_100-safe legacy tensor-core path)
// =====================================================================
__device__ __forceinline__ uint32_t smem_u32(const void* p) {
    uint32_t a;
    asm("{ .reg .u64 t; cvta.to.shared.u64 t, %1; cvt.u32.u64 %0, t; }"
        : "=r"(a) : "l"(p));
    return a;
}
__device__ __forceinline__ void ldmx4(uint32_t* r, uint32_t a) {
    asm volatile("ldmatrix.sync.aligned.m8n8.x4.shared.b16 {%0,%1,%2,%3}, [%4];"
                 : "=r"(r[0]), "=r"(r[1]), "=r"(r[2]), "=r"(r[3]) : "r"(a));
}
__device__ __forceinline__ void ldmx4t(uint32_t* r, uint32_t a) {
    asm volatile("ldmatrix.sync.aligned.m8n8.x4.trans.shared.b16 {%0,%1,%2,%3}, [%4];"
                 : "=r"(r[0]), "=r"(r[1]), "=r"(r[2]), "=r"(r[3]) : "r"(a));
}
__device__ __forceinline__ void ldmx2(uint32_t* r, uint32_t a) {
    asm volatile("ldmatrix.sync.aligned.m8n8.x2.shared.b16 {%0,%1}, [%2];"
                 : "=r"(r[0]), "=r"(r[1]) : "r"(a));
}
__device__ __forceinline__ void mma_bf16(float* c, const uint32_t* a,
                                         const uint32_t* b) {
    asm volatile(
        "mma.sync.aligned.m16n8k16.row.col.f32.bf16.bf16.f32 "
        "{%0,%1,%2,%3}, {%4,%5,%6,%7}, {%8,%9}, {%0,%1,%2,%3};"
        : "+f"(c[0]), "+f"(c[1]), "+f"(c[2]), "+f"(c[3])
        : "r"(a[0]), "r"(a[1]), "r"(a[2]), "r"(a[3]), "r"(b[0]), "r"(b[1]));
}
// float -> (hi, lo) bf16 split, packed pairwise
__device__ __forceinline__ void split2(float x, float y, uint32_t& h, uint32_t& l) {
    __nv_bfloat16 hx = __float2bfloat16(x);
    __nv_bfloat16 hy = __float2bfloat16(y);
    __nv_bfloat16 lx = __float2bfloat16(x - __bfloat162float(hx));
    __nv_bfloat16 ly = __float2bfloat16(y - __bfloat162float(hy));
    h = (uint32_t)__bfloat16_as_ushort(hx) | ((uint32_t)__bfloat16_as_ushort(hy) << 16);
    l = (uint32_t)__bfloat16_as_ushort(lx) | ((uint32_t)__bfloat16_as_ushort(ly) << 16);
}
// FMA-pipe exp2 (no MUFU)
__device__ __forceinline__ float fexp2(float t) {
    t = fmaxf(t, -126.0f);
    float r = t + 12582912.0f;             // 1.5 * 2^23
    int32_t ib = __float_as_int(r);
    float nf = r - 12582912.0f;
    float f = t - nf;                      // f in [-0.5, 0.5]
    float p = 0.00133336f;
    p = fmaf(p, f, 0.00961813f);
    p = fmaf(p, f, 0.05550411f);
    p = fmaf(p, f, 0.24022651f);
    p = fmaf(p, f, 0.69314718f);
    p = fmaf(p, f, 1.0f);
    return __int_as_float(__float_as_int(p) + (ib << 23));
}
#define L2E 1.4426950408889634f
// 16-byte cp.async
__device__ __forceinline__ void cpa16(uint32_t s, const void* g) {
    asm volatile("cp.async.cg.shared.global [%0], [%1], 16;" :: "r"(s), "l"(g));
}
#define CPA_WAIT() asm volatile( \
    "cp.async.commit_group;\n\tcp.async.wait_group 0;" ::: "memory")

// =====================================================================
// mma.sync split-bf16 GEMM.
// MODE 0: V proj  -> split bf16 hi/lo, (b,h,l,d)
// MODE 1: Q/K proj with RMSNorm+RoPE (+oscale) -> split bf16 hi/lo
// MODE 2: Wo proj -> fp32 row-major [8192,768]
// =====================================================================
#define AH_OFF 0
#define AL_OFF 18432
#define BH_OFF 36864
#define BL_OFF 46080
#define RN_OFF 55296
#define SMEM_MM (55296 + 512)

template <int MODE>
__global__ void __launch_bounds__(256)
mma_gemm(const float* __restrict__ Ag, const float* __restrict__ Wg,
         int w_off,
         const float* __restrict__ cosp, const float* __restrict__ sinp,
         const float* __restrict__ nw, float oscale,
         float* __restrict__ outp,
         unsigned short* __restrict__ oh, unsigned short* __restrict__ ol)
{
    extern __shared__ __align__(16) char sm[];
    const int tid = threadIdx.x;
    const int w = tid >> 5, lane = tid & 31;
    const int row0 = blockIdx.x * 128;
    const int head = blockIdx.y;
    const int c0 = w_off + head * 64;

    float acc[8][4] = {};

    const uint32_t sb = smem_u32(sm);
    const uint32_t a_row = (uint32_t)(w * 16 + (lane & 15));
    const uint32_t a_koff = (uint32_t)((lane >> 4) * 8);
    const uint32_t ah_base = sb + AH_OFF + (a_row * 72 + a_koff) * 2;
    const uint32_t al_base = sb + AL_OFF + (a_row * 72 + a_koff) * 2;
    const uint32_t b_row = (uint32_t)(lane & 7);
    const uint32_t b_koff = (uint32_t)(((lane >> 3) & 1) * 8);

    for (int kc = 0; kc < 12; kc++) {
        for (int e = tid; e < 2048; e += 256) {
            int r = e >> 4, c4 = e & 15;
            float4 v = *(const float4*)&Ag[(size_t)(row0 + r) * DIMC + kc * 64 + c4 * 4];
            uint32_t h0, l0, h1, l1;
            split2(v.x, v.y, h0, l0);
            split2(v.z, v.w, h1, l1);
            uint32_t off = (uint32_t)(r * 72 + c4 * 4) * 2;
            *(uint2*)(sm + AH_OFF + off) = make_uint2(h0, h1);
            *(uint2*)(sm + AL_OFF + off) = make_uint2(l0, l1);
        }
        for (int e = tid; e < 1024; e += 256) {
            int r = e >> 4, c4 = e & 15;
            float4 v = *(const float4*)&Wg[(size_t)(c0 + r) * DIMC + kc * 64 + c4 * 4];
            uint32_t h0, l0, h1, l1;
            split2(v.x, v.y, h0, l0);
            split2(v.z, v.w, h1, l1);
            uint32_t off = (uint32_t)(r * 72 + c4 * 4) * 2;
            *(uint2*)(sm + BH_OFF + off) = make_uint2(h0, h1);
            *(uint2*)(sm + BL_OFF + off) = make_uint2(l0, l1);
        }
        __syncthreads();

#pragma unroll
        for (int s = 0; s < 4; s++) {
            uint32_t ah[4], al[4];
            ldmx4(ah, ah_base + (uint32_t)(s * 16) * 2);
            ldmx4(al, al_base + (uint32_t)(s * 16) * 2);
#pragma unroll
            for (int j = 0; j < 8; j++) {
                uint32_t boff = ((uint32_t)(j * 8) + b_row) * 144 +
                                ((uint32_t)(s * 16) + b_koff) * 2;
                uint32_t bh[2], bl[2];
                ldmx2(bh, sb + BH_OFF + boff);
                ldmx2(bl, sb + BL_OFF + boff);
                mma_bf16(acc[j], ah, bh);
                mma_bf16(acc[j], ah, bl);
                mma_bf16(acc[j], al, bh);
            }
        }
        __syncthreads();
    }

    float* Cs = (float*)(sm + AH_OFF);     // [128][68]
    const int g = lane >> 2, tg = lane & 3;
#pragma unroll
    for (int j = 0; j < 8; j++) {
        Cs[(w * 16 + g) * 68 + j * 8 + tg * 2 + 0] = acc[j][0];
        Cs[(w * 16 + g) * 68 + j * 8 + tg * 2 + 1] = acc[j][1];
        Cs[(w * 16 + g + 8) * 68 + j * 8 + tg * 2 + 0] = acc[j][2];
        Cs[(w * 16 + g + 8) * 68 + j * 8 + tg * 2 + 1] = acc[j][3];
    }
    __syncthreads();

    float* rnp = (float*)(sm + RN_OFF);
    if (MODE == 1) {
        if (tid < 128) {
            float s = 0.f;
#pragma unroll 8
            for (int c = 0; c < 64; c++) { float v = Cs[tid * 68 + c]; s += v * v; }
            rnp[tid] = rsqrtf(s * (1.0f / 64.0f) + 1e-6f);
        }
        __syncthreads();
    }

    if (MODE == 2) {
        for (int e = tid; e < 8192; e += 256) {
            int r = e >> 6, d = e & 63;
            outp[(size_t)(row0 + r) * DIMC + head * 64 + d] = Cs[r * 68 + d];
        }
    } else {
        // split-bf16 output, 2 elements per iteration (d2 even)
        for (int e = tid; e < 4096; e += 256) {
            int r = e >> 5, d2 = (e & 31) << 1;
            int grow = row0 + r;
            int b = grow >> 11, l = grow & 2047;
            float o0, o1;
            if (MODE == 1) {
                float nrm = rnp[r];
                float v0 = Cs[r * 68 + d2] * nrm * nw[d2];
                float v1 = Cs[r * 68 + d2 + 1] * nrm * nw[d2 + 1];
                int dp = d2 ^ 32;
                float pv0 = Cs[r * 68 + dp] * nrm * nw[dp];
                float pv1 = Cs[r * 68 + dp + 1] * nrm * nw[dp + 1];
                float rh0 = (d2 < 32) ? -pv0 : pv0;
                float rh1 = (d2 < 32) ? -pv1 : pv1;
                float cv0 = cosp[(size_t)grow * 64 + d2];
                float cv1 = cosp[(size_t)grow * 64 + d2 + 1];
                float sv0 = sinp[(size_t)grow * 64 + d2];
                float sv1 = sinp[(size_t)grow * 64 + d2 + 1];
                o0 = (v0 * cv0 + rh0 * sv0) * oscale;
                o1 = (v1 * cv1 + rh1 * sv1) * oscale;
            } else {
                o0 = Cs[r * 68 + d2];
                o1 = Cs[r * 68 + d2 + 1];
            }
            uint32_t h, lo;
            split2(o0, o1, h, lo);
            size_t idx = (((size_t)(b * HC + head) * LQC + l) << 6) + d2;
            *(uint32_t*)(oh + idx) = h;
            *(uint32_t*)(ol + idx) = lo;
        }
    }
}

// =====================================================================
// Tensor-core flash attention v4: pre-split Q/K/V (no conversion in the
// mainloop), cp.async smem fills, 128x128 tiles, in-register P, 2 CTAs/SM.
// smem: Qh/Ql [128][72]bf16, Kh/Kl [128][72], Vh/Vl [128][72] = 110592 B
// =====================================================================
#define QH_OFF 0
#define QL_OFF 18432
#define KH_OFF 36864
#define KL_OFF 55296
#define VH_OFF 73728
#define VL_OFF 92160
#define FA_SMEM 110592

__global__ void __launch_bounds__(256, 2)
flash_mma(const unsigned short* __restrict__ gQh, const unsigned short* __restrict__ gQl,
          const unsigned short* __restrict__ gKh, const unsigned short* __restrict__ gKl,
          const unsigned short* __restrict__ gVh, const unsigned short* __restrict__ gVl,
          float* __restrict__ gAO)
{
    extern __shared__ __align__(16) char sm[];
    const uint32_t sb = smem_u32(sm);
    const int tid = threadIdx.x;
    const int w = tid >> 5, lane = tid & 31;
    const int bh = blockIdx.y;
    const int q0 = blockIdx.x * 128;
    const int g = lane >> 2, qd = lane & 3;

    const uint4* Qhb = (const uint4*)gQh + (size_t)bh * LQC * 8;
    const uint4* Qlb = (const uint4*)gQl + (size_t)bh * LQC * 8;
    const uint4* Khb = (const uint4*)gKh + (size_t)bh * LKC * 8;
    const uint4* Klb = (const uint4*)gKl + (size_t)bh * LKC * 8;
    const uint4* Vhb = (const uint4*)gVh + (size_t)bh * LKC * 8;
    const uint4* Vlb = (const uint4*)gVl + (size_t)bh * LKC * 8;

    // ---- Q tile: straight cp.async copy (already scaled+split) ----
    for (int e = tid; e < 1024; e += 256) {
        int r = e >> 3, c8 = e & 7;
        uint32_t so = (uint32_t)(r * 144 + c8 * 16);
        size_t gi = (size_t)(q0 + r) * 8 + c8;
        cpa16(sb + QH_OFF + so, Qhb + gi);
        cpa16(sb + QL_OFF + so, Qlb + gi);
    }
    CPA_WAIT();
    __syncthreads();

    float accO[8][4] = {};
    float m0 = -1e30f, m1 = -1e30f, l0 = 0.f, l1 = 0.f;

    const uint32_t arow = (uint32_t)(w * 16 + (lane & 15));
    const uint32_t akoff = (uint32_t)((lane >> 4) * 8);
    const uint32_t k_r = (uint32_t)(((lane >> 4) & 1) * 8 + (lane & 7));
    const uint32_t k_c = (uint32_t)(((lane >> 3) & 1) * 8);
    const uint32_t v_r = (uint32_t)(lane & 15);
    const uint32_t v_c = (uint32_t)(((lane >> 4) & 1) * 16);

    for (int k0 = 0; k0 < LKC; k0 += 128) {
        // ---- K/V tiles: pure cp.async copies ----
        for (int e = tid; e < 1024; e += 256) {
            int r = e >> 3, c8 = e & 7;
            uint32_t so = (uint32_t)(r * 144 + c8 * 16);
            size_t gi = (size_t)(k0 + r) * 8 + c8;
            cpa16(sb + KH_OFF + so, Khb + gi);
            cpa16(sb + KL_OFF + so, Klb + gi);
            cpa16(sb + VH_OFF + so, Vhb + gi);
            cpa16(sb + VL_OFF + so, Vlb + gi);
        }
        CPA_WAIT();
        __syncthreads();

#pragma unroll
        for (int half = 0; half < 2; half++) {
            // ---- S = Q K^T over 64 kv cols ----
            float accS[8][4];
#pragma unroll
            for (int j = 0; j < 8; j++) {
                accS[j][0] = 0.f; accS[j][1] = 0.f;
                accS[j][2] = 0.f; accS[j][3] = 0.f;
            }
#pragma unroll
            for (int s = 0; s < 4; s++) {
                uint32_t qh[4], ql[4];
                uint32_t qoff = (arow * 72 + (uint32_t)(s * 16) + akoff) * 2;
                ldmx4(qh, sb + QH_OFF + qoff);
                ldmx4(ql, sb + QL_OFF + qoff);
#pragma unroll
                for (int jp = 0; jp < 4; jp++) {
                    uint32_t koff = ((uint32_t)(half * 64 + jp * 16) + k_r) * 144 +
                                    ((uint32_t)(s * 16) + k_c) * 2;
                    uint32_t kh4[4], kl4[4];
                    ldmx4(kh4, sb + KH_OFF + koff);
                    ldmx4(kl4, sb + KL_OFF + koff);
                    mma_bf16(accS[jp * 2],     qh, kh4);
                    mma_bf16(accS[jp * 2],     qh, kl4);
                    mma_bf16(accS[jp * 2],     ql, kh4);
                    mma_bf16(accS[jp * 2 + 1], qh, kh4 + 2);
                    mma_bf16(accS[jp * 2 + 1], qh, kl4 + 2);
                    mma_bf16(accS[jp * 2 + 1], ql, kh4 + 2);
                }
            }

            // ---- online softmax (rows g and g+8), exp on FMA pipe ----
            float mx0 = -1e30f, mx1 = -1e30f;
#pragma unroll
            for (int j = 0; j < 8; j++) {
                mx0 = fmaxf(mx0, fmaxf(accS[j][0], accS[j][1]));
                mx1 = fmaxf(mx1, fmaxf(accS[j][2], accS[j][3]));
            }
            mx0 = fmaxf(mx0, __shfl_xor_sync(0xffffffffu, mx0, 1));
            mx0 = fmaxf(mx0, __shfl_xor_sync(0xffffffffu, mx0, 2));
            mx1 = fmaxf(mx1, __shfl_xor_sync(0xffffffffu, mx1, 1));
            mx1 = fmaxf(mx1, __shfl_xor_sync(0xffffffffu, mx1, 2));
            float m0n = fmaxf(m0, mx0), m1n = fmaxf(m1, mx1);
            float al0 = fexp2((m0 - m0n) * L2E);
            float al1 = fexp2((m1 - m1n) * L2E);
            float rs0 = 0.f, rs1 = 0.f;
#pragma unroll
            for (int j = 0; j < 8; j++) {
                float p0 = fexp2((accS[j][0] - m0n) * L2E);
                float p1 = fexp2((accS[j][1] - m0n) * L2E);
                float p2 = fexp2((accS[j][2] - m1n) * L2E);
                float p3 = fexp2((accS[j][3] - m1n) * L2E);
                rs0 += p0 + p1; rs1 += p2 + p3;
                accS[j][0] = p0; accS[j][1] = p1;
                accS[j][2] = p2; accS[j][3] = p3;
            }
            rs0 += __shfl_xor_sync(0xffffffffu, rs0, 1);
            rs0 += __shfl_xor_sync(0xffffffffu, rs0, 2);
            rs1 += __shfl_xor_sync(0xffffffffu, rs1, 1);
            rs1 += __shfl_xor_sync(0xffffffffu, rs1, 2);
            l0 = l0 * al0 + rs0;
            l1 = l1 * al1 + rs1;
            m0 = m0n; m1 = m1n;
#pragma unroll
            for (int j = 0; j < 8; j++) {
                accO[j][0] *= al0; accO[j][1] *= al0;
                accO[j][2] *= al1; accO[j][3] *= al1;
            }

            // ---- O += P V : P A-frags built in-register from accS ----
#pragma unroll
            for (int s = 0; s < 4; s++) {
                uint32_t ph[4], pl[4];
                split2(accS[2 * s][0],     accS[2 * s][1],     ph[0], pl[0]);
                split2(accS[2 * s][2],     accS[2 * s][3],     ph[1], pl[1]);
                split2(accS[2 * s + 1][0], accS[2 * s + 1][1], ph[2], pl[2]);
                split2(accS[2 * s + 1][2], accS[2 * s + 1][3], ph[3], pl[3]);
                uint32_t vro = ((uint32_t)(half * 64 + s * 16) + v_r) * 144;
#pragma unroll
                for (int jp = 0; jp < 4; jp++) {
                    uint32_t voff = vro + (uint32_t)(jp * 32) + v_c;
                    uint32_t vh4[4], vl4[4];
                    ldmx4t(vh4, sb + VH_OFF + voff);
                    ldmx4t(vl4, sb + VL_OFF + voff);
                    mma_bf16(accO[jp * 2],     ph, vh4);
                    mma_bf16(accO[jp * 2],     ph, vl4);
                    mma_bf16(accO[jp * 2],     pl, vh4);
                    mma_bf16(accO[jp * 2 + 1], ph, vh4 + 2);
                    mma_bf16(accO[jp * 2 + 1], ph, vl4 + 2);
                    mma_bf16(accO[jp * 2 + 1], pl, vh4 + 2);
                }
            }
        }
        __syncthreads();   // protect K/V before next tile's overwrite
    }

    // ---- normalize and write AO ----
    const int b = bh / HC, h = bh % HC;
    const float inv0 = 1.0f / l0, inv1 = 1.0f / l1;
    const size_t base0 = (size_t)(b * LQC + q0 + w * 16 + g) * DIMC + h * 64;
    const size_t base1 = base0 + (size_t)8 * DIMC;
#pragma unroll
    for (int j = 0; j < 8; j++) {
        *(float2*)&gAO[base0 + j * 8 + qd * 2] =
            make_float2(accO[j][0] * inv0, accO[j][1] * inv0);
        *(float2*)&gAO[base1 + j * 8 + qd * 2] =
            make_float2(accO[j][2] * inv1, accO[j][3] * inv1);
    }
}

// =====================================================================
// launch
// =====================================================================
extern "C" void kernel_launch(void* const* d_in, const int* in_sizes, int n_in,
                              void* d_out, int out_size)
{
    const float* queries = (const float*)d_in[0];
    const float* context = (const float*)d_in[1];
    const float* qcos    = (const float*)d_in[2];
    const float* qsin    = (const float*)d_in[3];
    const float* kcos    = (const float*)d_in[4];
    const float* ksin    = (const float*)d_in[5];
    const float* Wq      = (const float*)d_in[6];
    const float* Wkv     = (const float*)d_in[7];
    const float* Wo      = (const float*)d_in[8];
    const float* qnw     = (const float*)d_in[9];
    const float* knw     = (const float*)d_in[10];
    float* out = (float*)d_out;

    float* pAO;
    unsigned short *qh, *ql, *kh, *kl, *vh, *vl;
    cudaGetSymbolAddress((void**)&pAO, g_AO);
    cudaGetSymbolAddress((void**)&qh,  g_Qh);
    cudaGetSymbolAddress((void**)&ql,  g_Ql);
    cudaGetSymbolAddress((void**)&kh,  g_Kh);
    cudaGetSymbolAddress((void**)&kl,  g_Kl);
    cudaGetSymbolAddress((void**)&vh,  g_Vh);
    cudaGetSymbolAddress((void**)&vl,  g_Vl);

    cudaFuncSetAttribute(mma_gemm<0>, cudaFuncAttributeMaxDynamicSharedMemorySize, SMEM_MM);
    cudaFuncSetAttribute(mma_gemm<1>, cudaFuncAttributeMaxDynamicSharedMemorySize, SMEM_MM);
    cudaFuncSetAttribute(mma_gemm<2>, cudaFuncAttributeMaxDynamicSharedMemorySize, SMEM_MM);
    cudaFuncSetAttribute(flash_mma, cudaFuncAttributeMaxDynamicSharedMemorySize, FA_SMEM);

    dim3 blk(256);
    dim3 gg(NR / 128, HC);

    // Q: RMSNorm+RoPE, pre-scaled by 1/sqrt(64); K: scale 1; V: plain.
    mma_gemm<1><<<gg, blk, SMEM_MM>>>(queries, Wq,  0,    qcos, qsin, qnw,
                                      0.125f, (float*)0, qh, ql);
    mma_gemm<1><<<gg, blk, SMEM_MM>>>(context, Wkv, 0,    kcos, ksin, knw,
                                      1.0f, (float*)0, kh, kl);
    mma_gemm<0><<<gg, blk, SMEM_MM>>>(context, Wkv, DIMC,
                                      (const float*)0, (const float*)0,
                                      (const float*)0, 1.0f,
                                      (float*)0, vh, vl);

    flash_mma<<<dim3(LQC / 128, BC * HC), blk, FA_SMEM>>>(qh, ql, kh, kl, vh, vl, pAO);

    mma_gemm<2><<<gg, blk, SMEM_MM>>>(pAO, Wo, 0,
                                      (const float*)0, (const float*)0,
                                      (const float*)0, 1.0f,
                                      out, (unsigned short*)0, (unsigned short*)0);
}

// round 14
// speedup vs baseline: 1.3739x; 1.3739x over previous
#include <cuda_runtime.h>
#include <cuda_bf16.h>
#include <cuda_fp16.h>
#include <cstdint>
#include <cstddef>

#define DIMC 768
#define HC 12
#define HDC 64
#define BC 4
#define LQC 2048
#define LKC 2048
#define NR (BC * LQC)   // 8192 rows
#define NELT (BC * HC * LQC * HDC)

// ---------------- scratch (no allocations allowed) ----------------
// pre-split gemm operands (bf16 hi/lo)
__device__ unsigned short g_xqh[NR * DIMC], g_xql[NR * DIMC];     // queries
__device__ unsigned short g_xch[NR * DIMC], g_xcl[NR * DIMC];     // context
__device__ unsigned short g_aoh[NR * DIMC], g_aol[NR * DIMC];     // attn out
__device__ unsigned short g_wqh[DIMC * DIMC], g_wql[DIMC * DIMC];
__device__ unsigned short g_wkvh[2 * DIMC * DIMC], g_wkvl[2 * DIMC * DIMC];
__device__ unsigned short g_woh[DIMC * DIMC], g_wol[DIMC * DIMC];
// projection outputs: Q/K split bf16; V split fp16
__device__ unsigned short g_Qh[NELT], g_Ql[NELT];
__device__ unsigned short g_Kh[NELT], g_Kl[NELT];
__device__ unsigned short g_Vh[NELT], g_Vl[NELT];
__device__ float g_AO[BC * LQC * DIMC];      // (b,l,dim) fp32

// =====================================================================
// helpers
// =====================================================================
__device__ __forceinline__ uint32_t smem_u32(const void* p) {
    uint32_t a;
    asm("{ .reg .u64 t; cvta.to.shared.u64 t, %1; cvt.u32.u64 %0, t; }"
        : "=r"(a) : "l"(p));
    return a;
}
__device__ __forceinline__ void ldmx4(uint32_t* r, uint32_t a) {
    asm volatile("ldmatrix.sync.aligned.m8n8.x4.shared.b16 {%0,%1,%2,%3}, [%4];"
                 : "=r"(r[0]), "=r"(r[1]), "=r"(r[2]), "=r"(r[3]) : "r"(a));
}
__device__ __forceinline__ void ldmx4t(uint32_t* r, uint32_t a) {
    asm volatile("ldmatrix.sync.aligned.m8n8.x4.trans.shared.b16 {%0,%1,%2,%3}, [%4];"
                 : "=r"(r[0]), "=r"(r[1]), "=r"(r[2]), "=r"(r[3]) : "r"(a));
}
__device__ __forceinline__ void ldmx2(uint32_t* r, uint32_t a) {
    asm volatile("ldmatrix.sync.aligned.m8n8.x2.shared.b16 {%0,%1}, [%2];"
                 : "=r"(r[0]), "=r"(r[1]) : "r"(a));
}
__device__ __forceinline__ void mma_bf16(float* c, const uint32_t* a,
                                         const uint32_t* b) {
    asm volatile(
        "mma.sync.aligned.m16n8k16.row.col.f32.bf16.bf16.f32 "
        "{%0,%1,%2,%3}, {%4,%5,%6,%7}, {%8,%9}, {%0,%1,%2,%3};"
        : "+f"(c[0]), "+f"(c[1]), "+f"(c[2]), "+f"(c[3])
        : "r"(a[0]), "r"(a[1]), "r"(a[2]), "r"(a[3]), "r"(b[0]), "r"(b[1]));
}
__device__ __forceinline__ void mma_f16(float* c, const uint32_t* a,
                                        const uint32_t* b) {
    asm volatile(
        "mma.sync.aligned.m16n8k16.row.col.f32.f16.f16.f32 "
        "{%0,%1,%2,%3}, {%4,%5,%6,%7}, {%8,%9}, {%0,%1,%2,%3};"
        : "+f"(c[0]), "+f"(c[1]), "+f"(c[2]), "+f"(c[3])
        : "r"(a[0]), "r"(a[1]), "r"(a[2]), "r"(a[3]), "r"(b[0]), "r"(b[1]));
}
// float -> (hi, lo) bf16 split, packed pairwise
__device__ __forceinline__ void split2(float x, float y, uint32_t& h, uint32_t& l) {
    __nv_bfloat16 hx = __float2bfloat16(x);
    __nv_bfloat16 hy = __float2bfloat16(y);
    __nv_bfloat16 lx = __float2bfloat16(x - __bfloat162float(hx));
    __nv_bfloat16 ly = __float2bfloat16(y - __bfloat162float(hy));
    h = (uint32_t)__bfloat16_as_ushort(hx) | ((uint32_t)__bfloat16_as_ushort(hy) << 16);
    l = (uint32_t)__bfloat16_as_ushort(lx) | ((uint32_t)__bfloat16_as_ushort(ly) << 16);
}
// float -> (hi, lo) fp16 split, packed pairwise (for V)
__device__ __forceinline__ void split2h(float x, float y, uint32_t& h, uint32_t& l) {
    __half hx = __float2half_rn(x);
    __half hy = __float2half_rn(y);
    __half lx = __float2half_rn(x - __half2float(hx));
    __half ly = __float2half_rn(y - __half2float(hy));
    h = (uint32_t)__half_as_ushort(hx) | ((uint32_t)__half_as_ushort(hy) << 16);
    l = (uint32_t)__half_as_ushort(lx) | ((uint32_t)__half_as_ushort(ly) << 16);
}
__device__ __forceinline__ uint32_t f22h2(float x, float y) {
    __half2 h = __floats2half2_rn(x, y);
    return *(uint32_t*)&h;
}
// FMA-pipe exp2 (no MUFU)
__device__ __forceinline__ float fexp2(float t) {
    t = fmaxf(t, -126.0f);
    float r = t + 12582912.0f;             // 1.5 * 2^23
    int32_t ib = __float_as_int(r);
    float nf = r - 12582912.0f;
    float f = t - nf;                      // f in [-0.5, 0.5]
    float p = 0.00133336f;
    p = fmaf(p, f, 0.00961813f);
    p = fmaf(p, f, 0.05550411f);
    p = fmaf(p, f, 0.24022651f);
    p = fmaf(p, f, 0.69314718f);
    p = fmaf(p, f, 1.0f);
    return __int_as_float(__float_as_int(p) + (ib << 23));
}
#define L2E 1.4426950408889634f
__device__ __forceinline__ void cpa16(uint32_t s, const void* g) {
    asm volatile("cp.async.cg.shared.global [%0], [%1], 16;" :: "r"(s), "l"(g));
}
#define CPA_WAIT() asm volatile( \
    "cp.async.commit_group;\n\tcp.async.wait_group 0;" ::: "memory")

// =====================================================================
// fp32 -> split bf16 one-shot conversion (hoists ALL gemm splitting)
// =====================================================================
__global__ void __launch_bounds__(256)
cvt_split(const float4* __restrict__ x, uint2* __restrict__ hi,
          uint2* __restrict__ lo, int n4)
{
    int i = blockIdx.x * 256 + threadIdx.x;
    if (i >= n4) return;
    float4 v = x[i];
    uint32_t h0, l0, h1, l1;
    split2(v.x, v.y, h0, l0);
    split2(v.z, v.w, h1, l1);
    hi[i] = make_uint2(h0, h1);
    lo[i] = make_uint2(l0, l1);
}

// =====================================================================
// mma.sync split-bf16 GEMM with pre-split operands (pure cp.async loads).
// MODE 0: V proj  -> split fp16 hi/lo, (b,h,l,d)
// MODE 1: Q/K proj, RMSNorm+RoPE (+oscale) -> split bf16 hi/lo
// MODE 2: Wo proj -> fp32 row-major [8192,768]
// =====================================================================
#define AH_OFF 0
#define AL_OFF 18432
#define BH_OFF 36864
#define BL_OFF 46080
#define RN_OFF 55296
#define SMEM_MM (55296 + 512)

template <int MODE>
__global__ void __launch_bounds__(256)
mma_gemm(const unsigned short* __restrict__ Ahg, const unsigned short* __restrict__ Alg,
         const unsigned short* __restrict__ Whg, const unsigned short* __restrict__ Wlg,
         int w_off,
         const float* __restrict__ cosp, const float* __restrict__ sinp,
         const float* __restrict__ nw, float oscale,
         float* __restrict__ outp,
         unsigned short* __restrict__ oh, unsigned short* __restrict__ ol)
{
    extern __shared__ __align__(16) char sm[];
    const int tid = threadIdx.x;
    const int w = tid >> 5, lane = tid & 31;
    const int row0 = blockIdx.x * 128;
    const int head = blockIdx.y;
    const int c0 = w_off + head * 64;

    float acc[8][4] = {};

    const uint32_t sb = smem_u32(sm);
    const uint32_t a_row = (uint32_t)(w * 16 + (lane & 15));
    const uint32_t a_koff = (uint32_t)((lane >> 4) * 8);
    const uint32_t ah_base = sb + AH_OFF + (a_row * 72 + a_koff) * 2;
    const uint32_t al_base = sb + AL_OFF + (a_row * 72 + a_koff) * 2;
    const uint32_t b_row = (uint32_t)(lane & 7);
    const uint32_t b_koff = (uint32_t)(((lane >> 3) & 1) * 8);

    const uint4* Ah4 = (const uint4*)Ahg;
    const uint4* Al4 = (const uint4*)Alg;
    const uint4* Wh4 = (const uint4*)Whg;
    const uint4* Wl4 = (const uint4*)Wlg;

    for (int kc = 0; kc < 12; kc++) {
        // A chunk: 128 rows x 8 16B-chunks, hi+lo
        for (int e = tid; e < 1024; e += 256) {
            int r = e >> 3, c8 = e & 7;
            uint32_t so = (uint32_t)(r * 144 + c8 * 16);
            size_t gi = (size_t)(row0 + r) * 96 + kc * 8 + c8;
            cpa16(sb + AH_OFF + so, Ah4 + gi);
            cpa16(sb + AL_OFF + so, Al4 + gi);
        }
        // W chunk: 64 rows x 8 chunks, hi+lo
        for (int e = tid; e < 512; e += 256) {
            int r = e >> 3, c8 = e & 7;
            uint32_t so = (uint32_t)(r * 144 + c8 * 16);
            size_t gi = (size_t)(c0 + r) * 96 + kc * 8 + c8;
            cpa16(sb + BH_OFF + so, Wh4 + gi);
            cpa16(sb + BL_OFF + so, Wl4 + gi);
        }
        CPA_WAIT();
        __syncthreads();

#pragma unroll
        for (int s = 0; s < 4; s++) {
            uint32_t ah[4], al[4];
            ldmx4(ah, ah_base + (uint32_t)(s * 16) * 2);
            ldmx4(al, al_base + (uint32_t)(s * 16) * 2);
#pragma unroll
            for (int j = 0; j < 8; j++) {
                uint32_t boff = ((uint32_t)(j * 8) + b_row) * 144 +
                                ((uint32_t)(s * 16) + b_koff) * 2;
                uint32_t bh[2], bl[2];
                ldmx2(bh, sb + BH_OFF + boff);
                ldmx2(bl, sb + BL_OFF + boff);
                mma_bf16(acc[j], ah, bh);
                mma_bf16(acc[j], ah, bl);
                mma_bf16(acc[j], al, bh);
            }
        }
        __syncthreads();
    }

    float* Cs = (float*)(sm + AH_OFF);     // [128][68]
    const int g = lane >> 2, tg = lane & 3;
#pragma unroll
    for (int j = 0; j < 8; j++) {
        Cs[(w * 16 + g) * 68 + j * 8 + tg * 2 + 0] = acc[j][0];
        Cs[(w * 16 + g) * 68 + j * 8 + tg * 2 + 1] = acc[j][1];
        Cs[(w * 16 + g + 8) * 68 + j * 8 + tg * 2 + 0] = acc[j][2];
        Cs[(w * 16 + g + 8) * 68 + j * 8 + tg * 2 + 1] = acc[j][3];
    }
    __syncthreads();

    float* rnp = (float*)(sm + RN_OFF);
    if (MODE == 1) {
        if (tid < 128) {
            float s = 0.f;
#pragma unroll 8
            for (int c = 0; c < 64; c++) { float v = Cs[tid * 68 + c]; s += v * v; }
            rnp[tid] = rsqrtf(s * (1.0f / 64.0f) + 1e-6f);
        }
        __syncthreads();
    }

    if (MODE == 2) {
        for (int e = tid; e < 8192; e += 256) {
            int r = e >> 6, d = e & 63;
            outp[(size_t)(row0 + r) * DIMC + head * 64 + d] = Cs[r * 68 + d];
        }
    } else {
        for (int e = tid; e < 4096; e += 256) {
            int r = e >> 5, d2 = (e & 31) << 1;
            int grow = row0 + r;
            int b = grow >> 11, l = grow & 2047;
            float o0, o1;
            if (MODE == 1) {
                float nrm = rnp[r];
                float v0 = Cs[r * 68 + d2] * nrm * nw[d2];
                float v1 = Cs[r * 68 + d2 + 1] * nrm * nw[d2 + 1];
                int dp = d2 ^ 32;
                float pv0 = Cs[r * 68 + dp] * nrm * nw[dp];
                float pv1 = Cs[r * 68 + dp + 1] * nrm * nw[dp + 1];
                float rh0 = (d2 < 32) ? -pv0 : pv0;
                float rh1 = (d2 < 32) ? -pv1 : pv1;
                float2 cv = *(const float2*)&cosp[(size_t)grow * 64 + d2];
                float2 sv = *(const float2*)&sinp[(size_t)grow * 64 + d2];
                o0 = (v0 * cv.x + rh0 * sv.x) * oscale;
                o1 = (v1 * cv.y + rh1 * sv.y) * oscale;
            } else {
                o0 = Cs[r * 68 + d2];
                o1 = Cs[r * 68 + d2 + 1];
            }
            uint32_t h, lo;
            if (MODE == 0) split2h(o0, o1, h, lo);  // fp16 for V
            else           split2(o0, o1, h, lo);   // bf16 for Q/K
            size_t idx = (((size_t)(b * HC + head) * LQC + l) << 6) + d2;
            *(uint32_t*)(oh + idx) = h;
            *(uint32_t*)(ol + idx) = lo;
        }
    }
}

// =====================================================================
// Tensor-core flash attention v5: pre-split Q/K (bf16) + V (fp16),
// cp.async fills, 128x128 tiles, in-register P (fp16 single, 2-MMA PV),
// 2 CTAs/SM.
// smem: Qh/Ql, Kh/Kl (bf16), Vh/Vl (fp16), each [128][72]x2B = 110592 B
// =====================================================================
#define QH_OFF 0
#define QL_OFF 18432
#define KH_OFF 36864
#define KL_OFF 55296
#define VH_OFF 73728
#define VL_OFF 92160
#define FA_SMEM 110592

__global__ void __launch_bounds__(256, 2)
flash_mma(const unsigned short* __restrict__ gQh, const unsigned short* __restrict__ gQl,
          const unsigned short* __restrict__ gKh, const unsigned short* __restrict__ gKl,
          const unsigned short* __restrict__ gVh, const unsigned short* __restrict__ gVl,
          float* __restrict__ gAO)
{
    extern __shared__ __align__(16) char sm[];
    const uint32_t sb = smem_u32(sm);
    const int tid = threadIdx.x;
    const int w = tid >> 5, lane = tid & 31;
    const int bh = blockIdx.y;
    const int q0 = blockIdx.x * 128;
    const int g = lane >> 2, qd = lane & 3;

    const uint4* Qhb = (const uint4*)gQh + (size_t)bh * LQC * 8;
    const uint4* Qlb = (const uint4*)gQl + (size_t)bh * LQC * 8;
    const uint4* Khb = (const uint4*)gKh + (size_t)bh * LKC * 8;
    const uint4* Klb = (const uint4*)gKl + (size_t)bh * LKC * 8;
    const uint4* Vhb = (const uint4*)gVh + (size_t)bh * LKC * 8;
    const uint4* Vlb = (const uint4*)gVl + (size_t)bh * LKC * 8;

    for (int e = tid; e < 1024; e += 256) {
        int r = e >> 3, c8 = e & 7;
        uint32_t so = (uint32_t)(r * 144 + c8 * 16);
        size_t gi = (size_t)(q0 + r) * 8 + c8;
        cpa16(sb + QH_OFF + so, Qhb + gi);
        cpa16(sb + QL_OFF + so, Qlb + gi);
    }
    CPA_WAIT();
    __syncthreads();

    float accO[8][4] = {};
    float m0 = -1e30f, m1 = -1e30f, l0 = 0.f, l1 = 0.f;

    const uint32_t arow = (uint32_t)(w * 16 + (lane & 15));
    const uint32_t akoff = (uint32_t)((lane >> 4) * 8);
    const uint32_t k_r = (uint32_t)(((lane >> 4) & 1) * 8 + (lane & 7));
    const uint32_t k_c = (uint32_t)(((lane >> 3) & 1) * 8);
    const uint32_t v_r = (uint32_t)(lane & 15);
    const uint32_t v_c = (uint32_t)(((lane >> 4) & 1) * 16);

    for (int k0 = 0; k0 < LKC; k0 += 128) {
        for (int e = tid; e < 1024; e += 256) {
            int r = e >> 3, c8 = e & 7;
            uint32_t so = (uint32_t)(r * 144 + c8 * 16);
            size_t gi = (size_t)(k0 + r) * 8 + c8;
            cpa16(sb + KH_OFF + so, Khb + gi);
            cpa16(sb + KL_OFF + so, Klb + gi);
            cpa16(sb + VH_OFF + so, Vhb + gi);
            cpa16(sb + VL_OFF + so, Vlb + gi);
        }
        CPA_WAIT();
        __syncthreads();

#pragma unroll
        for (int half = 0; half < 2; half++) {
            // ---- S = Q K^T over 64 kv cols (split-bf16, 3 MMAs) ----
            float accS[8][4];
#pragma unroll
            for (int j = 0; j < 8; j++) {
                accS[j][0] = 0.f; accS[j][1] = 0.f;
                accS[j][2] = 0.f; accS[j][3] = 0.f;
            }
#pragma unroll
            for (int s = 0; s < 4; s++) {
                uint32_t qh[4], ql[4];
                uint32_t qoff = (arow * 72 + (uint32_t)(s * 16) + akoff) * 2;
                ldmx4(qh, sb + QH_OFF + qoff);
                ldmx4(ql, sb + QL_OFF + qoff);
#pragma unroll
                for (int jp = 0; jp < 4; jp++) {
                    uint32_t koff = ((uint32_t)(half * 64 + jp * 16) + k_r) * 144 +
                                    ((uint32_t)(s * 16) + k_c) * 2;
                    uint32_t kh4[4], kl4[4];
                    ldmx4(kh4, sb + KH_OFF + koff);
                    ldmx4(kl4, sb + KL_OFF + koff);
                    mma_bf16(accS[jp * 2],     qh, kh4);
                    mma_bf16(accS[jp * 2],     qh, kl4);
                    mma_bf16(accS[jp * 2],     ql, kh4);
                    mma_bf16(accS[jp * 2 + 1], qh, kh4 + 2);
                    mma_bf16(accS[jp * 2 + 1], qh, kl4 + 2);
                    mma_bf16(accS[jp * 2 + 1], ql, kh4 + 2);
                }
            }

            // ---- online softmax (rows g and g+8), exp on FMA pipe ----
            float mx0 = -1e30f, mx1 = -1e30f;
#pragma unroll
            for (int j = 0; j < 8; j++) {
                mx0 = fmaxf(mx0, fmaxf(accS[j][0], accS[j][1]));
                mx1 = fmaxf(mx1, fmaxf(accS[j][2], accS[j][3]));
            }
            mx0 = fmaxf(mx0, __shfl_xor_sync(0xffffffffu, mx0, 1));
            mx0 = fmaxf(mx0, __shfl_xor_sync(0xffffffffu, mx0, 2));
            mx1 = fmaxf(mx1, __shfl_xor_sync(0xffffffffu, mx1, 1));
            mx1 = fmaxf(mx1, __shfl_xor_sync(0xffffffffu, mx1, 2));
            float m0n = fmaxf(m0, mx0), m1n = fmaxf(m1, mx1);
            float al0 = fexp2((m0 - m0n) * L2E);
            float al1 = fexp2((m1 - m1n) * L2E);
            float rs0 = 0.f, rs1 = 0.f;
#pragma unroll
            for (int j = 0; j < 8; j++) {
                float p0 = fexp2((accS[j][0] - m0n) * L2E);
                float p1 = fexp2((accS[j][1] - m0n) * L2E);
                float p2 = fexp2((accS[j][2] - m1n) * L2E);
                float p3 = fexp2((accS[j][3] - m1n) * L2E);
                rs0 += p0 + p1; rs1 += p2 + p3;
                accS[j][0] = p0; accS[j][1] = p1;
                accS[j][2] = p2; accS[j][3] = p3;
            }
            rs0 += __shfl_xor_sync(0xffffffffu, rs0, 1);
            rs0 += __shfl_xor_sync(0xffffffffu, rs0, 2);
            rs1 += __shfl_xor_sync(0xffffffffu, rs1, 1);
            rs1 += __shfl_xor_sync(0xffffffffu, rs1, 2);
            l0 = l0 * al0 + rs0;
            l1 = l1 * al1 + rs1;
            m0 = m0n; m1 = m1n;
#pragma unroll
            for (int j = 0; j < 8; j++) {
                accO[j][0] *= al0; accO[j][1] *= al0;
                accO[j][2] *= al1; accO[j][3] *= al1;
            }

            // ---- O += P V : fp16 P (single) x split-fp16 V, 2 MMAs ----
#pragma unroll
            for (int s = 0; s < 4; s++) {
                uint32_t ph[4];
                ph[0] = f22h2(accS[2 * s][0],     accS[2 * s][1]);
                ph[1] = f22h2(accS[2 * s][2],     accS[2 * s][3]);
                ph[2] = f22h2(accS[2 * s + 1][0], accS[2 * s + 1][1]);
                ph[3] = f22h2(accS[2 * s + 1][2], accS[2 * s + 1][3]);
                uint32_t vro = ((uint32_t)(half * 64 + s * 16) + v_r) * 144;
#pragma unroll
                for (int jp = 0; jp < 4; jp++) {
                    uint32_t voff = vro + (uint32_t)(jp * 32) + v_c;
                    uint32_t vh4[4], vl4[4];
                    ldmx4t(vh4, sb + VH_OFF + voff);
                    ldmx4t(vl4, sb + VL_OFF + voff);
                    mma_f16(accO[jp * 2],     ph, vh4);
                    mma_f16(accO[jp * 2],     ph, vl4);
                    mma_f16(accO[jp * 2 + 1], ph, vh4 + 2);
                    mma_f16(accO[jp * 2 + 1], ph, vl4 + 2);
                }
            }
        }
        __syncthreads();   // protect K/V before next tile's overwrite
    }

    // ---- normalize and write AO ----
    const int b = bh / HC, h = bh % HC;
    const float inv0 = 1.0f / l0, inv1 = 1.0f / l1;
    const size_t base0 = (size_t)(b * LQC + q0 + w * 16 + g) * DIMC + h * 64;
    const size_t base1 = base0 + (size_t)8 * DIMC;
#pragma unroll
    for (int j = 0; j < 8; j++) {
        *(float2*)&gAO[base0 + j * 8 + qd * 2] =
            make_float2(accO[j][0] * inv0, accO[j][1] * inv0);
        *(float2*)&gAO[base1 + j * 8 + qd * 2] =
            make_float2(accO[j][2] * inv1, accO[j][3] * inv1);
    }
}

// =====================================================================
// launch
// =====================================================================
extern "C" void kernel_launch(void* const* d_in, const int* in_sizes, int n_in,
                              void* d_out, int out_size)
{
    const float* queries = (const float*)d_in[0];
    const float* context = (const float*)d_in[1];
    const float* qcos    = (const float*)d_in[2];
    const float* qsin    = (const float*)d_in[3];
    const float* kcos    = (const float*)d_in[4];
    const float* ksin    = (const float*)d_in[5];
    const float* Wq      = (const float*)d_in[6];
    const float* Wkv     = (const float*)d_in[7];
    const float* Wo      = (const float*)d_in[8];
    const float* qnw     = (const float*)d_in[9];
    const float* knw     = (const float*)d_in[10];
    float* out = (float*)d_out;

    float* pAO;
    unsigned short *xqh, *xql, *xch, *xcl, *aoh, *aol;
    unsigned short *wqh, *wql, *wkvh, *wkvl, *woh, *wol;
    unsigned short *qh, *ql, *kh, *kl, *vh, *vl;
    cudaGetSymbolAddress((void**)&pAO,  g_AO);
    cudaGetSymbolAddress((void**)&xqh,  g_xqh);
    cudaGetSymbolAddress((void**)&xql,  g_xql);
    cudaGetSymbolAddress((void**)&xch,  g_xch);
    cudaGetSymbolAddress((void**)&xcl,  g_xcl);
    cudaGetSymbolAddress((void**)&aoh,  g_aoh);
    cudaGetSymbolAddress((void**)&aol,  g_aol);
    cudaGetSymbolAddress((void**)&wqh,  g_wqh);
    cudaGetSymbolAddress((void**)&wql,  g_wql);
    cudaGetSymbolAddress((void**)&wkvh, g_wkvh);
    cudaGetSymbolAddress((void**)&wkvl, g_wkvl);
    cudaGetSymbolAddress((void**)&woh,  g_woh);
    cudaGetSymbolAddress((void**)&wol,  g_wol);
    cudaGetSymbolAddress((void**)&qh,   g_Qh);
    cudaGetSymbolAddress((void**)&ql,   g_Ql);
    cudaGetSymbolAddress((void**)&kh,   g_Kh);
    cudaGetSymbolAddress((void**)&kl,   g_Kl);
    cudaGetSymbolAddress((void**)&vh,   g_Vh);
    cudaGetSymbolAddress((void**)&vl,   g_Vl);

    cudaFuncSetAttribute(mma_gemm<0>, cudaFuncAttributeMaxDynamicSharedMemorySize, SMEM_MM);
    cudaFuncSetAttribute(mma_gemm<1>, cudaFuncAttributeMaxDynamicSharedMemorySize, SMEM_MM);
    cudaFuncSetAttribute(mma_gemm<2>, cudaFuncAttributeMaxDynamicSharedMemorySize, SMEM_MM);
    cudaFuncSetAttribute(flash_mma, cudaFuncAttributeMaxDynamicSharedMemorySize, FA_SMEM);

    const int ACT4 = NR * DIMC / 4;        // 1572864
    const int WQ4  = DIMC * DIMC / 4;      // 147456
    const int WKV4 = 2 * DIMC * DIMC / 4;  // 294912

    dim3 blk(256);
    dim3 gg(NR / 128, HC);

    // one-shot operand splitting
    cvt_split<<<ACT4 / 256, blk>>>((const float4*)queries, (uint2*)xqh, (uint2*)xql, ACT4);
    cvt_split<<<ACT4 / 256, blk>>>((const float4*)context, (uint2*)xch, (uint2*)xcl, ACT4);
    cvt_split<<<WQ4  / 256, blk>>>((const float4*)Wq,  (uint2*)wqh,  (uint2*)wql,  WQ4);
    cvt_split<<<WKV4 / 256, blk>>>((const float4*)Wkv, (uint2*)wkvh, (uint2*)wkvl, WKV4);
    cvt_split<<<WQ4  / 256, blk>>>((const float4*)Wo,  (uint2*)woh,  (uint2*)wol,  WQ4);

    // projections (Q pre-scaled by 1/sqrt(64))
    mma_gemm<1><<<gg, blk, SMEM_MM>>>(xqh, xql, wqh, wql, 0, qcos, qsin, qnw,
                                      0.125f, (float*)0, qh, ql);
    mma_gemm<1><<<gg, blk, SMEM_MM>>>(xch, xcl, wkvh, wkvl, 0, kcos, ksin, knw,
                                      1.0f, (float*)0, kh, kl);
    mma_gemm<0><<<gg, blk, SMEM_MM>>>(xch, xcl, wkvh, wkvl, DIMC,
                                      (const float*)0, (const float*)0,
                                      (const float*)0, 1.0f,
                                      (float*)0, vh, vl);

    flash_mma<<<dim3(LQC / 128, BC * HC), blk, FA_SMEM>>>(qh, ql, kh, kl, vh, vl, pAO);

    cvt_split<<<ACT4 / 256, blk>>>((const float4*)pAO, (uint2*)aoh, (uint2*)aol, ACT4);
    mma_gemm<2><<<gg, blk, SMEM_MM>>>(aoh, aol, woh, wol, 0,
                                      (const float*)0, (const float*)0,
                                      (const float*)0, 1.0f,
                                      out, (unsigned short*)0, (unsigned short*)0);
}

// round 15
// speedup vs baseline: 1.4283x; 1.0396x over previous
#include <cuda_runtime.h>
#include <cuda_bf16.h>
#include <cuda_fp16.h>
#include <cstdint>
#include <cstddef>

#define DIMC 768
#define HC 12
#define HDC 64
#define BC 4
#define LQC 2048
#define LKC 2048
#define NR (BC * LQC)   // 8192 rows
#define NELT (BC * HC * LQC * HDC)

// ---------------- scratch (no allocations allowed) ----------------
__device__ unsigned short g_xqh[NR * DIMC], g_xql[NR * DIMC];     // queries
__device__ unsigned short g_xch[NR * DIMC], g_xcl[NR * DIMC];     // context
__device__ unsigned short g_aoh[NR * DIMC], g_aol[NR * DIMC];     // attn out
__device__ unsigned short g_wqh[DIMC * DIMC], g_wql[DIMC * DIMC];
__device__ unsigned short g_wkvh[2 * DIMC * DIMC], g_wkvl[2 * DIMC * DIMC];
__device__ unsigned short g_woh[DIMC * DIMC], g_wol[DIMC * DIMC];
// projection outputs: Q/K split bf16; V split fp16
__device__ unsigned short g_Qh[NELT], g_Ql[NELT];
__device__ unsigned short g_Kh[NELT], g_Kl[NELT];
__device__ unsigned short g_Vh[NELT], g_Vl[NELT];
__device__ float g_AO[BC * LQC * DIMC];      // (b,l,dim) fp32

// =====================================================================
// helpers
// =====================================================================
__device__ __forceinline__ uint32_t smem_u32(const void* p) {
    uint32_t a;
    asm("{ .reg .u64 t; cvta.to.shared.u64 t, %1; cvt.u32.u64 %0, t; }"
        : "=r"(a) : "l"(p));
    return a;
}
__device__ __forceinline__ void ldmx4(uint32_t* r, uint32_t a) {
    asm volatile("ldmatrix.sync.aligned.m8n8.x4.shared.b16 {%0,%1,%2,%3}, [%4];"
                 : "=r"(r[0]), "=r"(r[1]), "=r"(r[2]), "=r"(r[3]) : "r"(a));
}
__device__ __forceinline__ void ldmx4t(uint32_t* r, uint32_t a) {
    asm volatile("ldmatrix.sync.aligned.m8n8.x4.trans.shared.b16 {%0,%1,%2,%3}, [%4];"
                 : "=r"(r[0]), "=r"(r[1]), "=r"(r[2]), "=r"(r[3]) : "r"(a));
}
__device__ __forceinline__ void ldmx2(uint32_t* r, uint32_t a) {
    asm volatile("ldmatrix.sync.aligned.m8n8.x2.shared.b16 {%0,%1}, [%2];"
                 : "=r"(r[0]), "=r"(r[1]) : "r"(a));
}
__device__ __forceinline__ void mma_bf16(float* c, const uint32_t* a,
                                         const uint32_t* b) {
    asm volatile(
        "mma.sync.aligned.m16n8k16.row.col.f32.bf16.bf16.f32 "
        "{%0,%1,%2,%3}, {%4,%5,%6,%7}, {%8,%9}, {%0,%1,%2,%3};"
        : "+f"(c[0]), "+f"(c[1]), "+f"(c[2]), "+f"(c[3])
        : "r"(a[0]), "r"(a[1]), "r"(a[2]), "r"(a[3]), "r"(b[0]), "r"(b[1]));
}
__device__ __forceinline__ void mma_f16(float* c, const uint32_t* a,
                                        const uint32_t* b) {
    asm volatile(
        "mma.sync.aligned.m16n8k16.row.col.f32.f16.f16.f32 "
        "{%0,%1,%2,%3}, {%4,%5,%6,%7}, {%8,%9}, {%0,%1,%2,%3};"
        : "+f"(c[0]), "+f"(c[1]), "+f"(c[2]), "+f"(c[3])
        : "r"(a[0]), "r"(a[1]), "r"(a[2]), "r"(a[3]), "r"(b[0]), "r"(b[1]));
}
// float -> (hi, lo) bf16 split, packed pairwise
__device__ __forceinline__ void split2(float x, float y, uint32_t& h, uint32_t& l) {
    __nv_bfloat16 hx = __float2bfloat16(x);
    __nv_bfloat16 hy = __float2bfloat16(y);
    __nv_bfloat16 lx = __float2bfloat16(x - __bfloat162float(hx));
    __nv_bfloat16 ly = __float2bfloat16(y - __bfloat162float(hy));
    h = (uint32_t)__bfloat16_as_ushort(hx) | ((uint32_t)__bfloat16_as_ushort(hy) << 16);
    l = (uint32_t)__bfloat16_as_ushort(lx) | ((uint32_t)__bfloat16_as_ushort(ly) << 16);
}
// float -> (hi, lo) fp16 split, packed pairwise (for V)
__device__ __forceinline__ void split2h(float x, float y, uint32_t& h, uint32_t& l) {
    __half hx = __float2half_rn(x);
    __half hy = __float2half_rn(y);
    __half lx = __float2half_rn(x - __half2float(hx));
    __half ly = __float2half_rn(y - __half2float(hy));
    h = (uint32_t)__half_as_ushort(hx) | ((uint32_t)__half_as_ushort(hy) << 16);
    l = (uint32_t)__half_as_ushort(lx) | ((uint32_t)__half_as_ushort(ly) << 16);
}
__device__ __forceinline__ uint32_t f22h2(float x, float y) {
    __half2 h = __floats2half2_rn(x, y);
    return *(uint32_t*)&h;
}
// FMA-pipe exp2 (no MUFU)
__device__ __forceinline__ float fexp2(float t) {
    t = fmaxf(t, -126.0f);
    float r = t + 12582912.0f;             // 1.5 * 2^23
    int32_t ib = __float_as_int(r);
    float nf = r - 12582912.0f;
    float f = t - nf;                      // f in [-0.5, 0.5]
    float p = 0.00133336f;
    p = fmaf(p, f, 0.00961813f);
    p = fmaf(p, f, 0.05550411f);
    p = fmaf(p, f, 0.24022651f);
    p = fmaf(p, f, 0.69314718f);
    p = fmaf(p, f, 1.0f);
    return __int_as_float(__float_as_int(p) + (ib << 23));
}
#define L2E 1.4426950408889634f
__device__ __forceinline__ void cpa16(uint32_t s, const void* g) {
    asm volatile("cp.async.cg.shared.global [%0], [%1], 16;" :: "r"(s), "l"(g));
}
#define CPA_COMMIT() asm volatile("cp.async.commit_group;" ::: "memory")
#define CPA_WAIT_ALL() asm volatile( \
    "cp.async.commit_group;\n\tcp.async.wait_group 0;" ::: "memory")
#define CPA_WG1() asm volatile("cp.async.wait_group 1;" ::: "memory")
#define CPA_WG0() asm volatile("cp.async.wait_group 0;" ::: "memory")

// =====================================================================
// fp32 -> split bf16 one-shot conversion
// =====================================================================
__global__ void __launch_bounds__(256)
cvt_split(const float4* __restrict__ x, uint2* __restrict__ hi,
          uint2* __restrict__ lo, int n4)
{
    int i = blockIdx.x * 256 + threadIdx.x;
    if (i >= n4) return;
    float4 v = x[i];
    uint32_t h0, l0, h1, l1;
    split2(v.x, v.y, h0, l0);
    split2(v.z, v.w, h1, l1);
    hi[i] = make_uint2(h0, h1);
    lo[i] = make_uint2(l0, l1);
}

// =====================================================================
// mma.sync split-bf16 GEMM with pre-split operands (unchanged from R14)
// =====================================================================
#define AH_OFF 0
#define AL_OFF 18432
#define BH_OFF 36864
#define BL_OFF 46080
#define RN_OFF 55296
#define SMEM_MM (55296 + 512)

template <int MODE>
__global__ void __launch_bounds__(256)
mma_gemm(const unsigned short* __restrict__ Ahg, const unsigned short* __restrict__ Alg,
         const unsigned short* __restrict__ Whg, const unsigned short* __restrict__ Wlg,
         int w_off,
         const float* __restrict__ cosp, const float* __restrict__ sinp,
         const float* __restrict__ nw, float oscale,
         float* __restrict__ outp,
         unsigned short* __restrict__ oh, unsigned short* __restrict__ ol)
{
    extern __shared__ __align__(16) char sm[];
    const int tid = threadIdx.x;
    const int w = tid >> 5, lane = tid & 31;
    const int row0 = blockIdx.x * 128;
    const int head = blockIdx.y;
    const int c0 = w_off + head * 64;

    float acc[8][4] = {};

    const uint32_t sb = smem_u32(sm);
    const uint32_t a_row = (uint32_t)(w * 16 + (lane & 15));
    const uint32_t a_koff = (uint32_t)((lane >> 4) * 8);
    const uint32_t ah_base = sb + AH_OFF + (a_row * 72 + a_koff) * 2;
    const uint32_t al_base = sb + AL_OFF + (a_row * 72 + a_koff) * 2;
    const uint32_t b_row = (uint32_t)(lane & 7);
    const uint32_t b_koff = (uint32_t)(((lane >> 3) & 1) * 8);

    const uint4* Ah4 = (const uint4*)Ahg;
    const uint4* Al4 = (const uint4*)Alg;
    const uint4* Wh4 = (const uint4*)Whg;
    const uint4* Wl4 = (const uint4*)Wlg;

    for (int kc = 0; kc < 12; kc++) {
        for (int e = tid; e < 1024; e += 256) {
            int r = e >> 3, c8 = e & 7;
            uint32_t so = (uint32_t)(r * 144 + c8 * 16);
            size_t gi = (size_t)(row0 + r) * 96 + kc * 8 + c8;
            cpa16(sb + AH_OFF + so, Ah4 + gi);
            cpa16(sb + AL_OFF + so, Al4 + gi);
        }
        for (int e = tid; e < 512; e += 256) {
            int r = e >> 3, c8 = e & 7;
            uint32_t so = (uint32_t)(r * 144 + c8 * 16);
            size_t gi = (size_t)(c0 + r) * 96 + kc * 8 + c8;
            cpa16(sb + BH_OFF + so, Wh4 + gi);
            cpa16(sb + BL_OFF + so, Wl4 + gi);
        }
        CPA_WAIT_ALL();
        __syncthreads();

#pragma unroll
        for (int s = 0; s < 4; s++) {
            uint32_t ah[4], al[4];
            ldmx4(ah, ah_base + (uint32_t)(s * 16) * 2);
            ldmx4(al, al_base + (uint32_t)(s * 16) * 2);
#pragma unroll
            for (int j = 0; j < 8; j++) {
                uint32_t boff = ((uint32_t)(j * 8) + b_row) * 144 +
                                ((uint32_t)(s * 16) + b_koff) * 2;
                uint32_t bh[2], bl[2];
                ldmx2(bh, sb + BH_OFF + boff);
                ldmx2(bl, sb + BL_OFF + boff);
                mma_bf16(acc[j], ah, bh);
                mma_bf16(acc[j], ah, bl);
                mma_bf16(acc[j], al, bh);
            }
        }
        __syncthreads();
    }

    float* Cs = (float*)(sm + AH_OFF);     // [128][68]
    const int g = lane >> 2, tg = lane & 3;
#pragma unroll
    for (int j = 0; j < 8; j++) {
        Cs[(w * 16 + g) * 68 + j * 8 + tg * 2 + 0] = acc[j][0];
        Cs[(w * 16 + g) * 68 + j * 8 + tg * 2 + 1] = acc[j][1];
        Cs[(w * 16 + g + 8) * 68 + j * 8 + tg * 2 + 0] = acc[j][2];
        Cs[(w * 16 + g + 8) * 68 + j * 8 + tg * 2 + 1] = acc[j][3];
    }
    __syncthreads();

    float* rnp = (float*)(sm + RN_OFF);
    if (MODE == 1) {
        if (tid < 128) {
            float s = 0.f;
#pragma unroll 8
            for (int c = 0; c < 64; c++) { float v = Cs[tid * 68 + c]; s += v * v; }
            rnp[tid] = rsqrtf(s * (1.0f / 64.0f) + 1e-6f);
        }
        __syncthreads();
    }

    if (MODE == 2) {
        for (int e = tid; e < 8192; e += 256) {
            int r = e >> 6, d = e & 63;
            outp[(size_t)(row0 + r) * DIMC + head * 64 + d] = Cs[r * 68 + d];
        }
    } else {
        for (int e = tid; e < 4096; e += 256) {
            int r = e >> 5, d2 = (e & 31) << 1;
            int grow = row0 + r;
            int b = grow >> 11, l = grow & 2047;
            float o0, o1;
            if (MODE == 1) {
                float nrm = rnp[r];
                float v0 = Cs[r * 68 + d2] * nrm * nw[d2];
                float v1 = Cs[r * 68 + d2 + 1] * nrm * nw[d2 + 1];
                int dp = d2 ^ 32;
                float pv0 = Cs[r * 68 + dp] * nrm * nw[dp];
                float pv1 = Cs[r * 68 + dp + 1] * nrm * nw[dp + 1];
                float rh0 = (d2 < 32) ? -pv0 : pv0;
                float rh1 = (d2 < 32) ? -pv1 : pv1;
                float2 cv = *(const float2*)&cosp[(size_t)grow * 64 + d2];
                float2 sv = *(const float2*)&sinp[(size_t)grow * 64 + d2];
                o0 = (v0 * cv.x + rh0 * sv.x) * oscale;
                o1 = (v1 * cv.y + rh1 * sv.y) * oscale;
            } else {
                o0 = Cs[r * 68 + d2];
                o1 = Cs[r * 68 + d2 + 1];
            }
            uint32_t h, lo;
            if (MODE == 0) split2h(o0, o1, h, lo);  // fp16 for V
            else           split2(o0, o1, h, lo);   // bf16 for Q/K
            size_t idx = (((size_t)(b * HC + head) * LQC + l) << 6) + d2;
            *(uint32_t*)(oh + idx) = h;
            *(uint32_t*)(ol + idx) = lo;
        }
    }
}

// =====================================================================
// Tensor-core flash attention v6: double-buffered 64-row K/V tiles.
// Pipeline: tile t+1's cp.async in flight while computing tile t.
// smem: QH/QL [128][72] + 2 stages x (KH/KL/VH/VL [64][72]) = 110592 B
//  -> 2 CTAs/SM.
// =====================================================================
#define QH_OFF 0
#define QL_OFF 18432
#define KV0_OFF 36864          // stage stride 36864; KH,KL,VH,VL at +0/+9216/+18432/+27648
#define KV_STRIDE 36864
#define FA_SMEM 110592
#define NTILE (LKC / 64)       // 32

__global__ void __launch_bounds__(256, 2)
flash_mma(const unsigned short* __restrict__ gQh, const unsigned short* __restrict__ gQl,
          const unsigned short* __restrict__ gKh, const unsigned short* __restrict__ gKl,
          const unsigned short* __restrict__ gVh, const unsigned short* __restrict__ gVl,
          float* __restrict__ gAO)
{
    extern __shared__ __align__(16) char sm[];
    const uint32_t sb = smem_u32(sm);
    const int tid = threadIdx.x;
    const int w = tid >> 5, lane = tid & 31;
    const int bh = blockIdx.y;
    const int q0 = blockIdx.x * 128;
    const int g = lane >> 2, qd = lane & 3;

    const uint4* Qhb = (const uint4*)gQh + (size_t)bh * LQC * 8;
    const uint4* Qlb = (const uint4*)gQl + (size_t)bh * LQC * 8;
    const uint4* Khb = (const uint4*)gKh + (size_t)bh * LKC * 8;
    const uint4* Klb = (const uint4*)gKl + (size_t)bh * LKC * 8;
    const uint4* Vhb = (const uint4*)gVh + (size_t)bh * LKC * 8;
    const uint4* Vlb = (const uint4*)gVl + (size_t)bh * LKC * 8;

    // ---- group 0: Q tile ----
    for (int e = tid; e < 1024; e += 256) {
        int r = e >> 3, c8 = e & 7;
        uint32_t so = (uint32_t)(r * 144 + c8 * 16);
        size_t gi = (size_t)(q0 + r) * 8 + c8;
        cpa16(sb + QH_OFF + so, Qhb + gi);
        cpa16(sb + QL_OFF + so, Qlb + gi);
    }
    CPA_COMMIT();
    // ---- group 1: KV tile 0 into stage 0 ----
    {
        uint32_t kb = sb + KV0_OFF;
        for (int e = tid; e < 512; e += 256) {
            int r = e >> 3, c8 = e & 7;
            uint32_t so = (uint32_t)(r * 144 + c8 * 16);
            size_t gi = (size_t)r * 8 + c8;
            cpa16(kb + so,         Khb + gi);
            cpa16(kb + 9216 + so,  Klb + gi);
            cpa16(kb + 18432 + so, Vhb + gi);
            cpa16(kb + 27648 + so, Vlb + gi);
        }
    }
    CPA_COMMIT();

    float accO[8][4] = {};
    float m0 = -1e30f, m1 = -1e30f, l0 = 0.f, l1 = 0.f;

    const uint32_t arow = (uint32_t)(w * 16 + (lane & 15));
    const uint32_t akoff = (uint32_t)((lane >> 4) * 8);
    const uint32_t k_r = (uint32_t)(((lane >> 4) & 1) * 8 + (lane & 7));
    const uint32_t k_c = (uint32_t)(((lane >> 3) & 1) * 8);
    const uint32_t v_r = (uint32_t)(lane & 15);
    const uint32_t v_c = (uint32_t)(((lane >> 4) & 1) * 16);

    for (int t = 0; t < NTILE; t++) {
        const int cur = t & 1;
        // prefetch tile t+1 into the other stage
        if (t + 1 < NTILE) {
            uint32_t kb = sb + KV0_OFF + (uint32_t)(1 - cur) * KV_STRIDE;
            for (int e = tid; e < 512; e += 256) {
                int r = e >> 3, c8 = e & 7;
                uint32_t so = (uint32_t)(r * 144 + c8 * 16);
                size_t gi = (size_t)((t + 1) * 64 + r) * 8 + c8;
                cpa16(kb + so,         Khb + gi);
                cpa16(kb + 9216 + so,  Klb + gi);
                cpa16(kb + 18432 + so, Vhb + gi);
                cpa16(kb + 27648 + so, Vlb + gi);
            }
            CPA_COMMIT();
            CPA_WG1();          // current tile (and Q) landed
        } else {
            CPA_WG0();
        }
        __syncthreads();

        const uint32_t kb = sb + KV0_OFF + (uint32_t)cur * KV_STRIDE;

        // ---- S = Q K^T over 64 kv cols (split-bf16, 3 MMAs) ----
        float accS[8][4];
#pragma unroll
        for (int j = 0; j < 8; j++) {
            accS[j][0] = 0.f; accS[j][1] = 0.f;
            accS[j][2] = 0.f; accS[j][3] = 0.f;
        }
#pragma unroll
        for (int s = 0; s < 4; s++) {
            uint32_t qh[4], ql[4];
            uint32_t qoff = (arow * 72 + (uint32_t)(s * 16) + akoff) * 2;
            ldmx4(qh, sb + QH_OFF + qoff);
            ldmx4(ql, sb + QL_OFF + qoff);
#pragma unroll
            for (int jp = 0; jp < 4; jp++) {
                uint32_t koff = ((uint32_t)(jp * 16) + k_r) * 144 +
                                ((uint32_t)(s * 16) + k_c) * 2;
                uint32_t kh4[4], kl4[4];
                ldmx4(kh4, kb + koff);
                ldmx4(kl4, kb + 9216 + koff);
                mma_bf16(accS[jp * 2],     qh, kh4);
                mma_bf16(accS[jp * 2],     qh, kl4);
                mma_bf16(accS[jp * 2],     ql, kh4);
                mma_bf16(accS[jp * 2 + 1], qh, kh4 + 2);
                mma_bf16(accS[jp * 2 + 1], qh, kl4 + 2);
                mma_bf16(accS[jp * 2 + 1], ql, kh4 + 2);
            }
        }

        // ---- online softmax (rows g and g+8), exp on FMA pipe ----
        float mx0 = -1e30f, mx1 = -1e30f;
#pragma unroll
        for (int j = 0; j < 8; j++) {
            mx0 = fmaxf(mx0, fmaxf(accS[j][0], accS[j][1]));
            mx1 = fmaxf(mx1, fmaxf(accS[j][2], accS[j][3]));
        }
        mx0 = fmaxf(mx0, __shfl_xor_sync(0xffffffffu, mx0, 1));
        mx0 = fmaxf(mx0, __shfl_xor_sync(0xffffffffu, mx0, 2));
        mx1 = fmaxf(mx1, __shfl_xor_sync(0xffffffffu, mx1, 1));
        mx1 = fmaxf(mx1, __shfl_xor_sync(0xffffffffu, mx1, 2));
        float m0n = fmaxf(m0, mx0), m1n = fmaxf(m1, mx1);
        float al0 = fexp2((m0 - m0n) * L2E);
        float al1 = fexp2((m1 - m1n) * L2E);
        float rs0 = 0.f, rs1 = 0.f;
#pragma unroll
        for (int j = 0; j < 8; j++) {
            float p0 = fexp2((accS[j][0] - m0n) * L2E);
            float p1 = fexp2((accS[j][1] - m0n) * L2E);
            float p2 = fexp2((accS[j][2] - m1n) * L2E);
            float p3 = fexp2((accS[j][3] - m1n) * L2E);
            rs0 += p0 + p1; rs1 += p2 + p3;
            accS[j][0] = p0; accS[j][1] = p1;
            accS[j][2] = p2; accS[j][3] = p3;
        }
        rs0 += __shfl_xor_sync(0xffffffffu, rs0, 1);
        rs0 += __shfl_xor_sync(0xffffffffu, rs0, 2);
        rs1 += __shfl_xor_sync(0xffffffffu, rs1, 1);
        rs1 += __shfl_xor_sync(0xffffffffu, rs1, 2);
        l0 = l0 * al0 + rs0;
        l1 = l1 * al1 + rs1;
        m0 = m0n; m1 = m1n;
#pragma unroll
        for (int j = 0; j < 8; j++) {
            accO[j][0] *= al0; accO[j][1] *= al0;
            accO[j][2] *= al1; accO[j][3] *= al1;
        }

        // ---- O += P V : fp16 P (in-register) x split-fp16 V, 2 MMAs ----
#pragma unroll
        for (int s = 0; s < 4; s++) {
            uint32_t ph[4];
            ph[0] = f22h2(accS[2 * s][0],     accS[2 * s][1]);
            ph[1] = f22h2(accS[2 * s][2],     accS[2 * s][3]);
            ph[2] = f22h2(accS[2 * s + 1][0], accS[2 * s + 1][1]);
            ph[3] = f22h2(accS[2 * s + 1][2], accS[2 * s + 1][3]);
            uint32_t vro = ((uint32_t)(s * 16) + v_r) * 144;
#pragma unroll
            for (int jp = 0; jp < 4; jp++) {
                uint32_t voff = vro + (uint32_t)(jp * 32) + v_c;
                uint32_t vh4[4], vl4[4];
                ldmx4t(vh4, kb + 18432 + voff);
                ldmx4t(vl4, kb + 27648 + voff);
                mma_f16(accO[jp * 2],     ph, vh4);
                mma_f16(accO[jp * 2],     ph, vl4);
                mma_f16(accO[jp * 2 + 1], ph, vh4 + 2);
                mma_f16(accO[jp * 2 + 1], ph, vl4 + 2);
            }
        }
        __syncthreads();   // all warps done with this stage before it is refilled
    }

    // ---- normalize and write AO ----
    const int b = bh / HC, h = bh % HC;
    const float inv0 = 1.0f / l0, inv1 = 1.0f / l1;
    const size_t base0 = (size_t)(b * LQC + q0 + w * 16 + g) * DIMC + h * 64;
    const size_t base1 = base0 + (size_t)8 * DIMC;
#pragma unroll
    for (int j = 0; j < 8; j++) {
        *(float2*)&gAO[base0 + j * 8 + qd * 2] =
            make_float2(accO[j][0] * inv0, accO[j][1] * inv0);
        *(float2*)&gAO[base1 + j * 8 + qd * 2] =
            make_float2(accO[j][2] * inv1, accO[j][3] * inv1);
    }
}

// =====================================================================
// launch
// =====================================================================
extern "C" void kernel_launch(void* const* d_in, const int* in_sizes, int n_in,
                              void* d_out, int out_size)
{
    const float* queries = (const float*)d_in[0];
    const float* context = (const float*)d_in[1];
    const float* qcos    = (const float*)d_in[2];
    const float* qsin    = (const float*)d_in[3];
    const float* kcos    = (const float*)d_in[4];
    const float* ksin    = (const float*)d_in[5];
    const float* Wq      = (const float*)d_in[6];
    const float* Wkv     = (const float*)d_in[7];
    const float* Wo      = (const float*)d_in[8];
    const float* qnw     = (const float*)d_in[9];
    const float* knw     = (const float*)d_in[10];
    float* out = (float*)d_out;

    float* pAO;
    unsigned short *xqh, *xql, *xch, *xcl, *aoh, *aol;
    unsigned short *wqh, *wql, *wkvh, *wkvl, *woh, *wol;
    unsigned short *qh, *ql, *kh, *kl, *vh, *vl;
    cudaGetSymbolAddress((void**)&pAO,  g_AO);
    cudaGetSymbolAddress((void**)&xqh,  g_xqh);
    cudaGetSymbolAddress((void**)&xql,  g_xql);
    cudaGetSymbolAddress((void**)&xch,  g_xch);
    cudaGetSymbolAddress((void**)&xcl,  g_xcl);
    cudaGetSymbolAddress((void**)&aoh,  g_aoh);
    cudaGetSymbolAddress((void**)&aol,  g_aol);
    cudaGetSymbolAddress((void**)&wqh,  g_wqh);
    cudaGetSymbolAddress((void**)&wql,  g_wql);
    cudaGetSymbolAddress((void**)&wkvh, g_wkvh);
    cudaGetSymbolAddress((void**)&wkvl, g_wkvl);
    cudaGetSymbolAddress((void**)&woh,  g_woh);
    cudaGetSymbolAddress((void**)&wol,  g_wol);
    cudaGetSymbolAddress((void**)&qh,   g_Qh);
    cudaGetSymbolAddress((void**)&ql,   g_Ql);
    cudaGetSymbolAddress((void**)&kh,   g_Kh);
    cudaGetSymbolAddress((void**)&kl,   g_Kl);
    cudaGetSymbolAddress((void**)&vh,   g_Vh);
    cudaGetSymbolAddress((void**)&vl,   g_Vl);

    cudaFuncSetAttribute(mma_gemm<0>, cudaFuncAttributeMaxDynamicSharedMemorySize, SMEM_MM);
    cudaFuncSetAttribute(mma_gemm<1>, cudaFuncAttributeMaxDynamicSharedMemorySize, SMEM_MM);
    cudaFuncSetAttribute(mma_gemm<2>, cudaFuncAttributeMaxDynamicSharedMemorySize, SMEM_MM);
    cudaFuncSetAttribute(flash_mma, cudaFuncAttributeMaxDynamicSharedMemorySize, FA_SMEM);

    const int ACT4 = NR * DIMC / 4;        // 1572864
    const int WQ4  = DIMC * DIMC / 4;      // 147456
    const int WKV4 = 2 * DIMC * DIMC / 4;  // 294912

    dim3 blk(256);
    dim3 gg(NR / 128, HC);

    cvt_split<<<ACT4 / 256, blk>>>((const float4*)queries, (uint2*)xqh, (uint2*)xql, ACT4);
    cvt_split<<<ACT4 / 256, blk>>>((const float4*)context, (uint2*)xch, (uint2*)xcl, ACT4);
    cvt_split<<<WQ4  / 256, blk>>>((const float4*)Wq,  (uint2*)wqh,  (uint2*)wql,  WQ4);
    cvt_split<<<WKV4 / 256, blk>>>((const float4*)Wkv, (uint2*)wkvh, (uint2*)wkvl, WKV4);
    cvt_split<<<WQ4  / 256, blk>>>((const float4*)Wo,  (uint2*)woh,  (uint2*)wol,  WQ4);

    mma_gemm<1><<<gg, blk, SMEM_MM>>>(xqh, xql, wqh, wql, 0, qcos, qsin, qnw,
                                      0.125f, (float*)0, qh, ql);
    mma_gemm<1><<<gg, blk, SMEM_MM>>>(xch, xcl, wkvh, wkvl, 0, kcos, ksin, knw,
                                      1.0f, (float*)0, kh, kl);
    mma_gemm<0><<<gg, blk, SMEM_MM>>>(xch, xcl, wkvh, wkvl, DIMC,
                                      (const float*)0, (const float*)0,
                                      (const float*)0, 1.0f,
                                      (float*)0, vh, vl);

    flash_mma<<<dim3(LQC / 128, BC * HC), blk, FA_SMEM>>>(qh, ql, kh, kl, vh, vl, pAO);

    cvt_split<<<ACT4 / 256, blk>>>((const float4*)pAO, (uint2*)aoh, (uint2*)aol, ACT4);
    mma_gemm<2><<<gg, blk, SMEM_MM>>>(aoh, aol, woh, wol, 0,
                                      (const float*)0, (const float*)0,
                                      (const float*)0, 1.0f,
                                      out, (unsigned short*)0, (unsigned short*)0);
}

// round 16
// speedup vs baseline: 1.5311x; 1.0720x over previous
#include <cuda_runtime.h>
#include <cuda_bf16.h>
#include <cuda_fp16.h>
#include <cstdint>
#include <cstddef>

#define DIMC 768
#define HC 12
#define HDC 64
#define BC 4
#define LQC 2048
#define LKC 2048
#define NR (BC * LQC)   // 8192 rows
#define NELT (BC * HC * LQC * HDC)

// ---------------- scratch (no allocations allowed) ----------------
__device__ unsigned short g_xqh[NR * DIMC], g_xql[NR * DIMC];     // queries
__device__ unsigned short g_xch[NR * DIMC], g_xcl[NR * DIMC];     // context
__device__ unsigned short g_aoh[NR * DIMC], g_aol[NR * DIMC];     // attn out
__device__ unsigned short g_wqh[DIMC * DIMC], g_wql[DIMC * DIMC];
__device__ unsigned short g_wkvh[2 * DIMC * DIMC], g_wkvl[2 * DIMC * DIMC];
__device__ unsigned short g_woh[DIMC * DIMC], g_wol[DIMC * DIMC];
// projection outputs: Q single fp16; K/V split fp16
__device__ unsigned short g_Qh[NELT];
__device__ unsigned short g_Kh[NELT], g_Kl[NELT];
__device__ unsigned short g_Vh[NELT], g_Vl[NELT];
__device__ float g_AO[BC * LQC * DIMC];      // (b,l,dim) fp32

// =====================================================================
// helpers
// =====================================================================
__device__ __forceinline__ uint32_t smem_u32(const void* p) {
    uint32_t a;
    asm("{ .reg .u64 t; cvta.to.shared.u64 t, %1; cvt.u32.u64 %0, t; }"
        : "=r"(a) : "l"(p));
    return a;
}
__device__ __forceinline__ void ldmx4(uint32_t* r, uint32_t a) {
    asm volatile("ldmatrix.sync.aligned.m8n8.x4.shared.b16 {%0,%1,%2,%3}, [%4];"
                 : "=r"(r[0]), "=r"(r[1]), "=r"(r[2]), "=r"(r[3]) : "r"(a));
}
__device__ __forceinline__ void ldmx4t(uint32_t* r, uint32_t a) {
    asm volatile("ldmatrix.sync.aligned.m8n8.x4.trans.shared.b16 {%0,%1,%2,%3}, [%4];"
                 : "=r"(r[0]), "=r"(r[1]), "=r"(r[2]), "=r"(r[3]) : "r"(a));
}
__device__ __forceinline__ void ldmx2(uint32_t* r, uint32_t a) {
    asm volatile("ldmatrix.sync.aligned.m8n8.x2.shared.b16 {%0,%1}, [%2];"
                 : "=r"(r[0]), "=r"(r[1]) : "r"(a));
}
__device__ __forceinline__ void mma_bf16(float* c, const uint32_t* a,
                                         const uint32_t* b) {
    asm volatile(
        "mma.sync.aligned.m16n8k16.row.col.f32.bf16.bf16.f32 "
        "{%0,%1,%2,%3}, {%4,%5,%6,%7}, {%8,%9}, {%0,%1,%2,%3};"
        : "+f"(c[0]), "+f"(c[1]), "+f"(c[2]), "+f"(c[3])
        : "r"(a[0]), "r"(a[1]), "r"(a[2]), "r"(a[3]), "r"(b[0]), "r"(b[1]));
}
__device__ __forceinline__ void mma_f16(float* c, const uint32_t* a,
                                        const uint32_t* b) {
    asm volatile(
        "mma.sync.aligned.m16n8k16.row.col.f32.f16.f16.f32 "
        "{%0,%1,%2,%3}, {%4,%5,%6,%7}, {%8,%9}, {%0,%1,%2,%3};"
        : "+f"(c[0]), "+f"(c[1]), "+f"(c[2]), "+f"(c[3])
        : "r"(a[0]), "r"(a[1]), "r"(a[2]), "r"(a[3]), "r"(b[0]), "r"(b[1]));
}
// float -> (hi, lo) bf16 split, packed pairwise
__device__ __forceinline__ void split2(float x, float y, uint32_t& h, uint32_t& l) {
    __nv_bfloat16 hx = __float2bfloat16(x);
    __nv_bfloat16 hy = __float2bfloat16(y);
    __nv_bfloat16 lx = __float2bfloat16(x - __bfloat162float(hx));
    __nv_bfloat16 ly = __float2bfloat16(y - __bfloat162float(hy));
    h = (uint32_t)__bfloat16_as_ushort(hx) | ((uint32_t)__bfloat16_as_ushort(hy) << 16);
    l = (uint32_t)__bfloat16_as_ushort(lx) | ((uint32_t)__bfloat16_as_ushort(ly) << 16);
}
// float -> (hi, lo) fp16 split, packed pairwise (for K/V)
__device__ __forceinline__ void split2h(float x, float y, uint32_t& h, uint32_t& l) {
    __half hx = __float2half_rn(x);
    __half hy = __float2half_rn(y);
    __half lx = __float2half_rn(x - __half2float(hx));
    __half ly = __float2half_rn(y - __half2float(hy));
    h = (uint32_t)__half_as_ushort(hx) | ((uint32_t)__half_as_ushort(hy) << 16);
    l = (uint32_t)__half_as_ushort(lx) | ((uint32_t)__half_as_ushort(ly) << 16);
}
__device__ __forceinline__ uint32_t f22h2(float x, float y) {
    __half2 h = __floats2half2_rn(x, y);
    return *(uint32_t*)&h;
}
// FMA-pipe exp2 (no MUFU)
__device__ __forceinline__ float fexp2(float t) {
    t = fmaxf(t, -126.0f);
    float r = t + 12582912.0f;             // 1.5 * 2^23
    int32_t ib = __float_as_int(r);
    float nf = r - 12582912.0f;
    float f = t - nf;                      // f in [-0.5, 0.5]
    float p = 0.00133336f;
    p = fmaf(p, f, 0.00961813f);
    p = fmaf(p, f, 0.05550411f);
    p = fmaf(p, f, 0.24022651f);
    p = fmaf(p, f, 0.69314718f);
    p = fmaf(p, f, 1.0f);
    return __int_as_float(__float_as_int(p) + (ib << 23));
}
#define L2E 1.4426950408889634f
__device__ __forceinline__ void cpa16(uint32_t s, const void* g) {
    asm volatile("cp.async.cg.shared.global [%0], [%1], 16;" :: "r"(s), "l"(g));
}
#define CPA_COMMIT() asm volatile("cp.async.commit_group;" ::: "memory")
#define CPA_WAIT_ALL() asm volatile( \
    "cp.async.commit_group;\n\tcp.async.wait_group 0;" ::: "memory")
#define CPA_WG1() asm volatile("cp.async.wait_group 1;" ::: "memory")
#define CPA_WG0() asm volatile("cp.async.wait_group 0;" ::: "memory")

// =====================================================================
// fp32 -> split bf16 one-shot conversion (gemm operands)
// =====================================================================
__global__ void __launch_bounds__(256)
cvt_split(const float4* __restrict__ x, uint2* __restrict__ hi,
          uint2* __restrict__ lo, int n4)
{
    int i = blockIdx.x * 256 + threadIdx.x;
    if (i >= n4) return;
    float4 v = x[i];
    uint32_t h0, l0, h1, l1;
    split2(v.x, v.y, h0, l0);
    split2(v.z, v.w, h1, l1);
    hi[i] = make_uint2(h0, h1);
    lo[i] = make_uint2(l0, l1);
}

// =====================================================================
// mma.sync split-bf16 GEMM with pre-split operands.
// MODE 0: V proj  -> split fp16 hi/lo, (b,h,l,d)
// MODE 1: K proj, RMSNorm+RoPE -> split fp16 hi/lo
// MODE 3: Q proj, RMSNorm+RoPE (+oscale) -> SINGLE fp16 (oh only)
// MODE 2: Wo proj -> fp32 row-major [8192,768]
// =====================================================================
#define AH_OFF 0
#define AL_OFF 18432
#define BH_OFF 36864
#define BL_OFF 46080
#define RN_OFF 55296
#define SMEM_MM (55296 + 512)

template <int MODE>
__global__ void __launch_bounds__(256)
mma_gemm(const unsigned short* __restrict__ Ahg, const unsigned short* __restrict__ Alg,
         const unsigned short* __restrict__ Whg, const unsigned short* __restrict__ Wlg,
         int w_off,
         const float* __restrict__ cosp, const float* __restrict__ sinp,
         const float* __restrict__ nw, float oscale,
         float* __restrict__ outp,
         unsigned short* __restrict__ oh, unsigned short* __restrict__ ol)
{
    extern __shared__ __align__(16) char sm[];
    const int tid = threadIdx.x;
    const int w = tid >> 5, lane = tid & 31;
    const int row0 = blockIdx.x * 128;
    const int head = blockIdx.y;
    const int c0 = w_off + head * 64;

    float acc[8][4] = {};

    const uint32_t sb = smem_u32(sm);
    const uint32_t a_row = (uint32_t)(w * 16 + (lane & 15));
    const uint32_t a_koff = (uint32_t)((lane >> 4) * 8);
    const uint32_t ah_base = sb + AH_OFF + (a_row * 72 + a_koff) * 2;
    const uint32_t al_base = sb + AL_OFF + (a_row * 72 + a_koff) * 2;
    const uint32_t b_row = (uint32_t)(lane & 7);
    const uint32_t b_koff = (uint32_t)(((lane >> 3) & 1) * 8);

    const uint4* Ah4 = (const uint4*)Ahg;
    const uint4* Al4 = (const uint4*)Alg;
    const uint4* Wh4 = (const uint4*)Whg;
    const uint4* Wl4 = (const uint4*)Wlg;

    for (int kc = 0; kc < 12; kc++) {
        for (int e = tid; e < 1024; e += 256) {
            int r = e >> 3, c8 = e & 7;
            uint32_t so = (uint32_t)(r * 144 + c8 * 16);
            size_t gi = (size_t)(row0 + r) * 96 + kc * 8 + c8;
            cpa16(sb + AH_OFF + so, Ah4 + gi);
            cpa16(sb + AL_OFF + so, Al4 + gi);
        }
        for (int e = tid; e < 512; e += 256) {
            int r = e >> 3, c8 = e & 7;
            uint32_t so = (uint32_t)(r * 144 + c8 * 16);
            size_t gi = (size_t)(c0 + r) * 96 + kc * 8 + c8;
            cpa16(sb + BH_OFF + so, Wh4 + gi);
            cpa16(sb + BL_OFF + so, Wl4 + gi);
        }
        CPA_WAIT_ALL();
        __syncthreads();

#pragma unroll
        for (int s = 0; s < 4; s++) {
            uint32_t ah[4], al[4];
            ldmx4(ah, ah_base + (uint32_t)(s * 16) * 2);
            ldmx4(al, al_base + (uint32_t)(s * 16) * 2);
#pragma unroll
            for (int j = 0; j < 8; j++) {
                uint32_t boff = ((uint32_t)(j * 8) + b_row) * 144 +
                                ((uint32_t)(s * 16) + b_koff) * 2;
                uint32_t bh[2], bl[2];
                ldmx2(bh, sb + BH_OFF + boff);
                ldmx2(bl, sb + BL_OFF + boff);
                mma_bf16(acc[j], ah, bh);
                mma_bf16(acc[j], ah, bl);
                mma_bf16(acc[j], al, bh);
            }
        }
        __syncthreads();
    }

    float* Cs = (float*)(sm + AH_OFF);     // [128][68]
    const int g = lane >> 2, tg = lane & 3;
#pragma unroll
    for (int j = 0; j < 8; j++) {
        Cs[(w * 16 + g) * 68 + j * 8 + tg * 2 + 0] = acc[j][0];
        Cs[(w * 16 + g) * 68 + j * 8 + tg * 2 + 1] = acc[j][1];
        Cs[(w * 16 + g + 8) * 68 + j * 8 + tg * 2 + 0] = acc[j][2];
        Cs[(w * 16 + g + 8) * 68 + j * 8 + tg * 2 + 1] = acc[j][3];
    }
    __syncthreads();

    float* rnp = (float*)(sm + RN_OFF);
    if (MODE == 1 || MODE == 3) {
        if (tid < 128) {
            float s = 0.f;
#pragma unroll 8
            for (int c = 0; c < 64; c++) { float v = Cs[tid * 68 + c]; s += v * v; }
            rnp[tid] = rsqrtf(s * (1.0f / 64.0f) + 1e-6f);
        }
        __syncthreads();
    }

    if (MODE == 2) {
        for (int e = tid; e < 8192; e += 256) {
            int r = e >> 6, d = e & 63;
            outp[(size_t)(row0 + r) * DIMC + head * 64 + d] = Cs[r * 68 + d];
        }
    } else {
        for (int e = tid; e < 4096; e += 256) {
            int r = e >> 5, d2 = (e & 31) << 1;
            int grow = row0 + r;
            int b = grow >> 11, l = grow & 2047;
            float o0, o1;
            if (MODE == 1 || MODE == 3) {
                float nrm = rnp[r];
                float v0 = Cs[r * 68 + d2] * nrm * nw[d2];
                float v1 = Cs[r * 68 + d2 + 1] * nrm * nw[d2 + 1];
                int dp = d2 ^ 32;
                float pv0 = Cs[r * 68 + dp] * nrm * nw[dp];
                float pv1 = Cs[r * 68 + dp + 1] * nrm * nw[dp + 1];
                float rh0 = (d2 < 32) ? -pv0 : pv0;
                float rh1 = (d2 < 32) ? -pv1 : pv1;
                float2 cv = *(const float2*)&cosp[(size_t)grow * 64 + d2];
                float2 sv = *(const float2*)&sinp[(size_t)grow * 64 + d2];
                o0 = (v0 * cv.x + rh0 * sv.x) * oscale;
                o1 = (v1 * cv.y + rh1 * sv.y) * oscale;
            } else {
                o0 = Cs[r * 68 + d2];
                o1 = Cs[r * 68 + d2 + 1];
            }
            size_t idx = (((size_t)(b * HC + head) * LQC + l) << 6) + d2;
            if (MODE == 3) {
                *(uint32_t*)(oh + idx) = f22h2(o0, o1);      // single fp16 Q
            } else {
                uint32_t h, lo;
                split2h(o0, o1, h, lo);                      // split fp16 K/V
                *(uint32_t*)(oh + idx) = h;
                *(uint32_t*)(ol + idx) = lo;
            }
        }
    }
}

// =====================================================================
// Tensor-core flash attention v7: Q single fp16, K split fp16 (2-MMA QK),
// V split fp16 (2-MMA PV), double-buffered 64-row K/V tiles.
// smem: Q [128][72] + 2 stages x (KH/KL/VH/VL [64][72]) = 92160 B
//  -> 2 CTAs/SM.
// =====================================================================
#define Q_OFF 0
#define KV0_OFF 18432
#define KV_STRIDE 36864
#define FA_SMEM 92160
#define NTILE (LKC / 64)       // 32

__global__ void __launch_bounds__(256, 2)
flash_mma(const unsigned short* __restrict__ gQh,
          const unsigned short* __restrict__ gKh, const unsigned short* __restrict__ gKl,
          const unsigned short* __restrict__ gVh, const unsigned short* __restrict__ gVl,
          float* __restrict__ gAO)
{
    extern __shared__ __align__(16) char sm[];
    const uint32_t sb = smem_u32(sm);
    const int tid = threadIdx.x;
    const int w = tid >> 5, lane = tid & 31;
    const int bh = blockIdx.y;
    const int q0 = blockIdx.x * 128;
    const int g = lane >> 2, qd = lane & 3;

    const uint4* Qhb = (const uint4*)gQh + (size_t)bh * LQC * 8;
    const uint4* Khb = (const uint4*)gKh + (size_t)bh * LKC * 8;
    const uint4* Klb = (const uint4*)gKl + (size_t)bh * LKC * 8;
    const uint4* Vhb = (const uint4*)gVh + (size_t)bh * LKC * 8;
    const uint4* Vlb = (const uint4*)gVl + (size_t)bh * LKC * 8;

    // ---- group 0: Q tile (single fp16) ----
    for (int e = tid; e < 1024; e += 256) {
        int r = e >> 3, c8 = e & 7;
        uint32_t so = (uint32_t)(r * 144 + c8 * 16);
        size_t gi = (size_t)(q0 + r) * 8 + c8;
        cpa16(sb + Q_OFF + so, Qhb + gi);
    }
    CPA_COMMIT();
    // ---- group 1: KV tile 0 into stage 0 ----
    {
        uint32_t kb = sb + KV0_OFF;
        for (int e = tid; e < 512; e += 256) {
            int r = e >> 3, c8 = e & 7;
            uint32_t so = (uint32_t)(r * 144 + c8 * 16);
            size_t gi = (size_t)r * 8 + c8;
            cpa16(kb + so,         Khb + gi);
            cpa16(kb + 9216 + so,  Klb + gi);
            cpa16(kb + 18432 + so, Vhb + gi);
            cpa16(kb + 27648 + so, Vlb + gi);
        }
    }
    CPA_COMMIT();

    float accO[8][4] = {};
    float m0 = -1e30f, m1 = -1e30f, l0 = 0.f, l1 = 0.f;

    const uint32_t arow = (uint32_t)(w * 16 + (lane & 15));
    const uint32_t akoff = (uint32_t)((lane >> 4) * 8);
    const uint32_t k_r = (uint32_t)(((lane >> 4) & 1) * 8 + (lane & 7));
    const uint32_t k_c = (uint32_t)(((lane >> 3) & 1) * 8);
    const uint32_t v_r = (uint32_t)(lane & 15);
    const uint32_t v_c = (uint32_t)(((lane >> 4) & 1) * 16);

    for (int t = 0; t < NTILE; t++) {
        const int cur = t & 1;
        if (t + 1 < NTILE) {
            uint32_t kb = sb + KV0_OFF + (uint32_t)(1 - cur) * KV_STRIDE;
            for (int e = tid; e < 512; e += 256) {
                int r = e >> 3, c8 = e & 7;
                uint32_t so = (uint32_t)(r * 144 + c8 * 16);
                size_t gi = (size_t)((t + 1) * 64 + r) * 8 + c8;
                cpa16(kb + so,         Khb + gi);
                cpa16(kb + 9216 + so,  Klb + gi);
                cpa16(kb + 18432 + so, Vhb + gi);
                cpa16(kb + 27648 + so, Vlb + gi);
            }
            CPA_COMMIT();
            CPA_WG1();
        } else {
            CPA_WG0();
        }
        __syncthreads();

        const uint32_t kb = sb + KV0_OFF + (uint32_t)cur * KV_STRIDE;

        // ---- S = Q K^T over 64 kv cols (fp16, 2 MMAs/step) ----
        float accS[8][4];
#pragma unroll
        for (int j = 0; j < 8; j++) {
            accS[j][0] = 0.f; accS[j][1] = 0.f;
            accS[j][2] = 0.f; accS[j][3] = 0.f;
        }
#pragma unroll
        for (int s = 0; s < 4; s++) {
            uint32_t qf[4];
            uint32_t qoff = (arow * 72 + (uint32_t)(s * 16) + akoff) * 2;
            ldmx4(qf, sb + Q_OFF + qoff);
#pragma unroll
            for (int jp = 0; jp < 4; jp++) {
                uint32_t koff = ((uint32_t)(jp * 16) + k_r) * 144 +
                                ((uint32_t)(s * 16) + k_c) * 2;
                uint32_t kh4[4], kl4[4];
                ldmx4(kh4, kb + koff);
                ldmx4(kl4, kb + 9216 + koff);
                mma_f16(accS[jp * 2],     qf, kh4);
                mma_f16(accS[jp * 2],     qf, kl4);
                mma_f16(accS[jp * 2 + 1], qf, kh4 + 2);
                mma_f16(accS[jp * 2 + 1], qf, kl4 + 2);
            }
        }

        // ---- online softmax (rows g and g+8), exp on FMA pipe ----
        float mx0 = -1e30f, mx1 = -1e30f;
#pragma unroll
        for (int j = 0; j < 8; j++) {
            mx0 = fmaxf(mx0, fmaxf(accS[j][0], accS[j][1]));
            mx1 = fmaxf(mx1, fmaxf(accS[j][2], accS[j][3]));
        }
        mx0 = fmaxf(mx0, __shfl_xor_sync(0xffffffffu, mx0, 1));
        mx0 = fmaxf(mx0, __shfl_xor_sync(0xffffffffu, mx0, 2));
        mx1 = fmaxf(mx1, __shfl_xor_sync(0xffffffffu, mx1, 1));
        mx1 = fmaxf(mx1, __shfl_xor_sync(0xffffffffu, mx1, 2));
        float m0n = fmaxf(m0, mx0), m1n = fmaxf(m1, mx1);
        float al0 = fexp2((m0 - m0n) * L2E);
        float al1 = fexp2((m1 - m1n) * L2E);
        float rs0 = 0.f, rs1 = 0.f;
#pragma unroll
        for (int j = 0; j < 8; j++) {
            float p0 = fexp2((accS[j][0] - m0n) * L2E);
            float p1 = fexp2((accS[j][1] - m0n) * L2E);
            float p2 = fexp2((accS[j][2] - m1n) * L2E);
            float p3 = fexp2((accS[j][3] - m1n) * L2E);
            rs0 += p0 + p1; rs1 += p2 + p3;
            accS[j][0] = p0; accS[j][1] = p1;
            accS[j][2] = p2; accS[j][3] = p3;
        }
        rs0 += __shfl_xor_sync(0xffffffffu, rs0, 1);
        rs0 += __shfl_xor_sync(0xffffffffu, rs0, 2);
        rs1 += __shfl_xor_sync(0xffffffffu, rs1, 1);
        rs1 += __shfl_xor_sync(0xffffffffu, rs1, 2);
        l0 = l0 * al0 + rs0;
        l1 = l1 * al1 + rs1;
        m0 = m0n; m1 = m1n;
#pragma unroll
        for (int j = 0; j < 8; j++) {
            accO[j][0] *= al0; accO[j][1] *= al0;
            accO[j][2] *= al1; accO[j][3] *= al1;
        }

        // ---- O += P V : fp16 P (in-register) x split-fp16 V, 2 MMAs ----
#pragma unroll
        for (int s = 0; s < 4; s++) {
            uint32_t ph[4];
            ph[0] = f22h2(accS[2 * s][0],     accS[2 * s][1]);
            ph[1] = f22h2(accS[2 * s][2],     accS[2 * s][3]);
            ph[2] = f22h2(accS[2 * s + 1][0], accS[2 * s + 1][1]);
            ph[3] = f22h2(accS[2 * s + 1][2], accS[2 * s + 1][3]);
            uint32_t vro = ((uint32_t)(s * 16) + v_r) * 144;
#pragma unroll
            for (int jp = 0; jp < 4; jp++) {
                uint32_t voff = vro + (uint32_t)(jp * 32) + v_c;
                uint32_t vh4[4], vl4[4];
                ldmx4t(vh4, kb + 18432 + voff);
                ldmx4t(vl4, kb + 27648 + voff);
                mma_f16(accO[jp * 2],     ph, vh4);
                mma_f16(accO[jp * 2],     ph, vl4);
                mma_f16(accO[jp * 2 + 1], ph, vh4 + 2);
                mma_f16(accO[jp * 2 + 1], ph, vl4 + 2);
            }
        }
        __syncthreads();   // all warps done with this stage before refill
    }

    // ---- normalize and write AO ----
    const int b = bh / HC, h = bh % HC;
    const float inv0 = 1.0f / l0, inv1 = 1.0f / l1;
    const size_t base0 = (size_t)(b * LQC + q0 + w * 16 + g) * DIMC + h * 64;
    const size_t base1 = base0 + (size_t)8 * DIMC;
#pragma unroll
    for (int j = 0; j < 8; j++) {
        *(float2*)&gAO[base0 + j * 8 + qd * 2] =
            make_float2(accO[j][0] * inv0, accO[j][1] * inv0);
        *(float2*)&gAO[base1 + j * 8 + qd * 2] =
            make_float2(accO[j][2] * inv1, accO[j][3] * inv1);
    }
}

// =====================================================================
// launch
// =====================================================================
extern "C" void kernel_launch(void* const* d_in, const int* in_sizes, int n_in,
                              void* d_out, int out_size)
{
    const float* queries = (const float*)d_in[0];
    const float* context = (const float*)d_in[1];
    const float* qcos    = (const float*)d_in[2];
    const float* qsin    = (const float*)d_in[3];
    const float* kcos    = (const float*)d_in[4];
    const float* ksin    = (const float*)d_in[5];
    const float* Wq      = (const float*)d_in[6];
    const float* Wkv     = (const float*)d_in[7];
    const float* Wo      = (const float*)d_in[8];
    const float* qnw     = (const float*)d_in[9];
    const float* knw     = (const float*)d_in[10];
    float* out = (float*)d_out;

    float* pAO;
    unsigned short *xqh, *xql, *xch, *xcl, *aoh, *aol;
    unsigned short *wqh, *wql, *wkvh, *wkvl, *woh, *wol;
    unsigned short *qh, *kh, *kl, *vh, *vl;
    cudaGetSymbolAddress((void**)&pAO,  g_AO);
    cudaGetSymbolAddress((void**)&xqh,  g_xqh);
    cudaGetSymbolAddress((void**)&xql,  g_xql);
    cudaGetSymbolAddress((void**)&xch,  g_xch);
    cudaGetSymbolAddress((void**)&xcl,  g_xcl);
    cudaGetSymbolAddress((void**)&aoh,  g_aoh);
    cudaGetSymbolAddress((void**)&aol,  g_aol);
    cudaGetSymbolAddress((void**)&wqh,  g_wqh);
    cudaGetSymbolAddress((void**)&wql,  g_wql);
    cudaGetSymbolAddress((void**)&wkvh, g_wkvh);
    cudaGetSymbolAddress((void**)&wkvl, g_wkvl);
    cudaGetSymbolAddress((void**)&woh,  g_woh);
    cudaGetSymbolAddress((void**)&wol,  g_wol);
    cudaGetSymbolAddress((void**)&qh,   g_Qh);
    cudaGetSymbolAddress((void**)&kh,   g_Kh);
    cudaGetSymbolAddress((void**)&kl,   g_Kl);
    cudaGetSymbolAddress((void**)&vh,   g_Vh);
    cudaGetSymbolAddress((void**)&vl,   g_Vl);

    cudaFuncSetAttribute(mma_gemm<0>, cudaFuncAttributeMaxDynamicSharedMemorySize, SMEM_MM);
    cudaFuncSetAttribute(mma_gemm<1>, cudaFuncAttributeMaxDynamicSharedMemorySize, SMEM_MM);
    cudaFuncSetAttribute(mma_gemm<2>, cudaFuncAttributeMaxDynamicSharedMemorySize, SMEM_MM);
    cudaFuncSetAttribute(mma_gemm<3>, cudaFuncAttributeMaxDynamicSharedMemorySize, SMEM_MM);
    cudaFuncSetAttribute(flash_mma, cudaFuncAttributeMaxDynamicSharedMemorySize, FA_SMEM);

    const int ACT4 = NR * DIMC / 4;        // 1572864
    const int WQ4  = DIMC * DIMC / 4;      // 147456
    const int WKV4 = 2 * DIMC * DIMC / 4;  // 294912

    dim3 blk(256);
    dim3 gg(NR / 128, HC);

    cvt_split<<<ACT4 / 256, blk>>>((const float4*)queries, (uint2*)xqh, (uint2*)xql, ACT4);
    cvt_split<<<ACT4 / 256, blk>>>((const float4*)context, (uint2*)xch, (uint2*)xcl, ACT4);
    cvt_split<<<WQ4  / 256, blk>>>((const float4*)Wq,  (uint2*)wqh,  (uint2*)wql,  WQ4);
    cvt_split<<<WKV4 / 256, blk>>>((const float4*)Wkv, (uint2*)wkvh, (uint2*)wkvl, WKV4);
    cvt_split<<<WQ4  / 256, blk>>>((const float4*)Wo,  (uint2*)woh,  (uint2*)wol,  WQ4);

    // Q: single fp16 (pre-scaled by 1/sqrt(64)); K: split fp16; V: split fp16
    mma_gemm<3><<<gg, blk, SMEM_MM>>>(xqh, xql, wqh, wql, 0, qcos, qsin, qnw,
                                      0.125f, (float*)0, qh, (unsigned short*)0);
    mma_gemm<1><<<gg, blk, SMEM_MM>>>(xch, xcl, wkvh, wkvl, 0, kcos, ksin, knw,
                                      1.0f, (float*)0, kh, kl);
    mma_gemm<0><<<gg, blk, SMEM_MM>>>(xch, xcl, wkvh, wkvl, DIMC,
                                      (const float*)0, (const float*)0,
                                      (const float*)0, 1.0f,
                                      (float*)0, vh, vl);

    flash_mma<<<dim3(LQC / 128, BC * HC), blk, FA_SMEM>>>(qh, kh, kl, vh, vl, pAO);

    cvt_split<<<ACT4 / 256, blk>>>((const float4*)pAO, (uint2*)aoh, (uint2*)aol, ACT4);
    mma_gemm<2><<<gg, blk, SMEM_MM>>>(aoh, aol, woh, wol, 0,
                                      (const float*)0, (const float*)0,
                                      (const float*)0, 1.0f,
                                      out, (unsigned short*)0, (unsigned short*)0);
}